// round 12
// baseline (speedup 1.0000x reference)
#include <cuda_runtime.h>
#include <cuda_bf16.h>
#include <math.h>
#include <stdint.h>

#define NNODE 50000
#define DDIM  256
#define HH    8
#define EE    500000
#define QKVW  768
#define ATT_SCALE 0.17677669529663687f  // 1/sqrt(32)

#define SCB   512                       // scan elements per block
#define NSCB  ((NNODE + SCB - 1) / SCB) // 98

// ======================= device scratch ==========================================
__device__ float g_bcat[2][QKVW];
__device__ __nv_bfloat16 g_WcatT_hi[2][(size_t)QKVW * DDIM];  // [n][k], n = Q|K'|V'
__device__ __nv_bfloat16 g_WcatT_lo[2][(size_t)QKVW * DDIM];
__device__ __nv_bfloat16 g_WaT_hi[2][(size_t)DDIM * DDIM];
__device__ __nv_bfloat16 g_WaT_lo[2][(size_t)DDIM * DDIM];
__device__ float g_QKV[2][(size_t)NNODE * QKVW];  // fp32: Q(256)|K'(256)|V'(256)
__device__ float g_h[2][(size_t)NNODE * DDIM];    // fp32 aggregated messages
__device__ float g_trans[2][(size_t)NNODE * DDIM];
// CSR-by-destination scratch
__device__ int g_deg[2][NNODE];
__device__ int g_rows[2][NNODE + 1];
__device__ int g_cursor[2][NNODE];
__device__ int g_esrc[2][EE];
__device__ int g_bsum[2][NSCB];
__device__ int g_boff[2][NSCB];

// ======================= PTX helpers (base-target safe) ==========================
__device__ __forceinline__ uint32_t smem_u32(const void* p) {
    uint32_t a;
    asm("{ .reg .u64 t; cvta.to.shared.u64 t, %1; cvt.u32.u64 %0, t; }" : "=r"(a) : "l"(p));
    return a;
}
__device__ __forceinline__ void ldm_x4(uint32_t* r, uint32_t addr) {
    asm volatile("ldmatrix.sync.aligned.m8n8.x4.shared.b16 {%0,%1,%2,%3}, [%4];"
                 : "=r"(r[0]), "=r"(r[1]), "=r"(r[2]), "=r"(r[3]) : "r"(addr));
}
__device__ __forceinline__ void mma_bf16(float* c, const uint32_t* a, const uint32_t* b) {
    asm volatile("mma.sync.aligned.m16n8k16.row.col.f32.bf16.bf16.f32 "
                 "{%0,%1,%2,%3}, {%4,%5,%6,%7}, {%8,%9}, {%0,%1,%2,%3};"
                 : "+f"(c[0]), "+f"(c[1]), "+f"(c[2]), "+f"(c[3])
                 : "r"(a[0]), "r"(a[1]), "r"(a[2]), "r"(a[3]), "r"(b[0]), "r"(b[1]));
}

// split 8 fp32 into bf16 hi/lo packed uint4s
__device__ __forceinline__ void split8(const float4& v0, const float4& v1,
                                       uint4& hiq, uint4& loq) {
    float f[8] = {v0.x, v0.y, v0.z, v0.w, v1.x, v1.y, v1.z, v1.w};
    __nv_bfloat162 hh[4], ll[4];
    #pragma unroll
    for (int j = 0; j < 4; ++j) {
        __nv_bfloat16 h0 = __float2bfloat16(f[2 * j]);
        __nv_bfloat16 h1 = __float2bfloat16(f[2 * j + 1]);
        __nv_bfloat16 l0 = __float2bfloat16(f[2 * j]     - __bfloat162float(h0));
        __nv_bfloat16 l1 = __float2bfloat16(f[2 * j + 1] - __bfloat162float(h1));
        hh[j] = __halves2bfloat162(h0, h1);
        ll[j] = __halves2bfloat162(l0, l1);
    }
    hiq = *(const uint4*)hh;
    loq = *(const uint4*)ll;
}

// ======================= 1. prep: fold + transpose + bf16 split ==================
__global__ __launch_bounds__(256) void prep_kernel(
    const float* __restrict__ Wk, const float* __restrict__ bk,
    const float* __restrict__ Wq, const float* __restrict__ bq,
    const float* __restrict__ Wv, const float* __restrict__ bv,
    const float* __restrict__ Wa,
    const float* __restrict__ w_att, const float* __restrict__ w_msg)
{
    const int t = blockIdx.y;
    const int n = blockIdx.x;
    const int k = threadIdx.x;

    float val;
    if (n < 768) {
        if (n < 256) {
            val = Wq[((size_t)t * 256 + k) * 256 + n];
        } else {
            const int j = (n - 256) & 255;
            const int h = j >> 5, jj = j & 31;
            const float* W = (n < 512) ? Wk : Wv;
            const float* wm = ((n < 512) ? w_att : w_msg) + ((size_t)(t * 8 + h)) * 1024 + jj;
            const float* wrow = W + ((size_t)t * 256 + k) * 256 + h * 32;
            float a = 0.f;
            #pragma unroll 8
            for (int i = 0; i < 32; ++i) a += wrow[i] * wm[i * 32];
            val = a;
        }
        __nv_bfloat16 hi = __float2bfloat16(val);
        __nv_bfloat16 lo = __float2bfloat16(val - __bfloat162float(hi));
        g_WcatT_hi[t][(size_t)n * 256 + k] = hi;
        g_WcatT_lo[t][(size_t)n * 256 + k] = lo;
        if (k == 0) {
            float b;
            if (n < 256) b = bq[t * 256 + n];
            else {
                const int j = (n - 256) & 255;
                const int h = j >> 5, jj = j & 31;
                const float* bb = (n < 512) ? bk : bv;
                const float* wm = ((n < 512) ? w_att : w_msg) + ((size_t)(t * 8 + h)) * 1024 + jj;
                float a = 0.f;
                #pragma unroll 8
                for (int i = 0; i < 32; ++i) a += bb[t * 256 + h * 32 + i] * wm[i * 32];
                b = a;
            }
            g_bcat[t][n] = b;
        }
    } else {
        const int nn = n - 768;
        val = Wa[((size_t)t * 256 + k) * 256 + nn];
        __nv_bfloat16 hi = __float2bfloat16(val);
        __nv_bfloat16 lo = __float2bfloat16(val - __bfloat162float(hi));
        g_WaT_hi[t][(size_t)nn * 256 + k] = hi;
        g_WaT_lo[t][(size_t)nn * 256 + k] = lo;
    }
}

// ======================= 2. CSR build ============================================
__global__ void zerodeg_kernel()
{
    int i = blockIdx.x * blockDim.x + threadIdx.x;
    if (i < 2 * NNODE) ((int*)g_deg)[i] = 0;
}

__global__ void hist_kernel(const int* __restrict__ dst)
{
    const int et = blockIdx.y;
    int e = blockIdx.x * blockDim.x + threadIdx.x;
    if (e >= EE) return;
    atomicAdd(&g_deg[et][dst[(long)et * EE + e]], 1);
}

// phase A: per-block exclusive scan of 512 degs; local offsets + block totals
__global__ __launch_bounds__(SCB) void scanA_kernel()
{
    const int et = blockIdx.y;
    const int b = blockIdx.x;
    const int tid = threadIdx.x;
    const int idx = b * SCB + tid;
    const int lane = tid & 31, w = tid >> 5;

    int d = (idx < NNODE) ? g_deg[et][idx] : 0;
    int x = d;
    #pragma unroll
    for (int o = 1; o < 32; o <<= 1) {
        int n = __shfl_up_sync(0xffffffffu, x, o);
        if (lane >= o) x += n;
    }
    __shared__ int ws[SCB / 32];
    if (lane == 31) ws[w] = x;
    __syncthreads();
    if (w == 0) {
        int y = (lane < SCB / 32) ? ws[lane] : 0;
        #pragma unroll
        for (int o = 1; o < SCB / 32; o <<= 1) {
            int n = __shfl_up_sync(0xffffffffu, y, o);
            if (lane >= o) y += n;
        }
        if (lane < SCB / 32) ws[lane] = y;
    }
    __syncthreads();
    const int incl = x + (w > 0 ? ws[w - 1] : 0);
    if (idx < NNODE) g_rows[et][idx] = incl - d;
    if (tid == SCB - 1) g_bsum[et][b] = incl;
}

// phase B: scan the NSCB block totals (one block per etype)
__global__ __launch_bounds__(128) void scanB_kernel()
{
    const int et = blockIdx.x;
    const int t = threadIdx.x;
    const int lane = t & 31, w = t >> 5;
    int v = (t < NSCB) ? g_bsum[et][t] : 0;
    int x = v;
    #pragma unroll
    for (int o = 1; o < 32; o <<= 1) {
        int n = __shfl_up_sync(0xffffffffu, x, o);
        if (lane >= o) x += n;
    }
    __shared__ int ws[4];
    if (lane == 31) ws[w] = x;
    __syncthreads();
    int add = 0;
    #pragma unroll
    for (int i = 0; i < 4; ++i) if (i < w) add += ws[i];
    const int incl = x + add;
    if (t < NSCB) g_boff[et][t] = incl - v;
    if (t == NSCB - 1) g_rows[et][NNODE] = incl;
}

// phase C: add block offsets; emit rows + cursor
__global__ __launch_bounds__(SCB) void scanC_kernel()
{
    const int et = blockIdx.y;
    const int b = blockIdx.x;
    const int idx = b * SCB + threadIdx.x;
    if (idx >= NNODE) return;
    const int r = g_rows[et][idx] + g_boff[et][b];
    g_rows[et][idx] = r;
    g_cursor[et][idx] = r;
}

__global__ void scatter_kernel(const int* __restrict__ src, const int* __restrict__ dst)
{
    const int et = blockIdx.y;
    int e = blockIdx.x * blockDim.x + threadIdx.x;
    if (e >= EE) return;
    int s = src[(long)et * EE + e];
    int d = dst[(long)et * EE + e];
    int pos = atomicAdd(&g_cursor[et][d], 1);
    g_esrc[et][pos] = s;
}

// ======================= 3. warp-per-dst aggregation (2-edge unroll) ==============
__device__ __forceinline__ float dot8(const float4& qa, const float4& qb,
                                      const float4& ka, const float4& kb) {
    return qa.x * ka.x + qa.y * ka.y + qa.z * ka.z + qa.w * ka.w
         + qb.x * kb.x + qb.y * kb.y + qb.z * kb.z + qb.w * kb.w;
}

__global__ __launch_bounds__(256) void agg_kernel(const float* __restrict__ mu)
{
    const int et = blockIdx.y;
    const int dt = 1 - et;
    const int warp = threadIdx.x >> 5;
    const int lane = threadIdx.x & 31;
    const int node = blockIdx.x * 8 + warp;
    if (node >= NNODE) return;

    const int r0 = g_rows[et][node];
    const int r1 = g_rows[et][node + 1];

    const int h = lane >> 2;
    const int base = lane * 8;
    const float muh = mu[et * 8 + h] * ATT_SCALE;

    float acc[8];
    #pragma unroll
    for (int j = 0; j < 8; ++j) acc[j] = 0.f;
    float wsum = 0.f;

    if (r0 < r1) {
        const float* qrow = g_QKV[dt] + (size_t)node * QKVW + base;
        const float4 qa = *(const float4*)qrow;
        const float4 qb = *(const float4*)(qrow + 4);
        const int* __restrict__ ep = g_esrc[et];
        const float* __restrict__ kvbase = g_QKV[et];

        int j = r0;
        for (; j + 1 < r1; j += 2) {
            const int s0 = ep[j];
            const int s1 = ep[j + 1];
            const float* kr0 = kvbase + (size_t)s0 * QKVW + 256 + base;
            const float* kr1 = kvbase + (size_t)s1 * QKVW + 256 + base;
            float4 ka0 = *(const float4*)kr0;
            float4 kb0 = *(const float4*)(kr0 + 4);
            float4 va0 = *(const float4*)(kr0 + 256);
            float4 vb0 = *(const float4*)(kr0 + 260);
            float4 ka1 = *(const float4*)kr1;
            float4 kb1 = *(const float4*)(kr1 + 4);
            float4 va1 = *(const float4*)(kr1 + 256);
            float4 vb1 = *(const float4*)(kr1 + 260);

            float p0 = dot8(qa, qb, ka0, kb0);
            float p1 = dot8(qa, qb, ka1, kb1);
            p0 += __shfl_xor_sync(0xffffffffu, p0, 1);
            p1 += __shfl_xor_sync(0xffffffffu, p1, 1);
            p0 += __shfl_xor_sync(0xffffffffu, p0, 2);
            p1 += __shfl_xor_sync(0xffffffffu, p1, 2);

            float w0 = expf(p0 * muh);
            float w1 = expf(p1 * muh);
            wsum += w0 + w1;
            acc[0] += w0 * va0.x + w1 * va1.x;
            acc[1] += w0 * va0.y + w1 * va1.y;
            acc[2] += w0 * va0.z + w1 * va1.z;
            acc[3] += w0 * va0.w + w1 * va1.w;
            acc[4] += w0 * vb0.x + w1 * vb1.x;
            acc[5] += w0 * vb0.y + w1 * vb1.y;
            acc[6] += w0 * vb0.z + w1 * vb1.z;
            acc[7] += w0 * vb0.w + w1 * vb1.w;
        }
        if (j < r1) {
            const int s0 = ep[j];
            const float* kr0 = kvbase + (size_t)s0 * QKVW + 256 + base;
            float4 ka0 = *(const float4*)kr0;
            float4 kb0 = *(const float4*)(kr0 + 4);
            float4 va0 = *(const float4*)(kr0 + 256);
            float4 vb0 = *(const float4*)(kr0 + 260);
            float p0 = dot8(qa, qb, ka0, kb0);
            p0 += __shfl_xor_sync(0xffffffffu, p0, 1);
            p0 += __shfl_xor_sync(0xffffffffu, p0, 2);
            float w0 = expf(p0 * muh);
            wsum += w0;
            acc[0] += w0 * va0.x;  acc[1] += w0 * va0.y;
            acc[2] += w0 * va0.z;  acc[3] += w0 * va0.w;
            acc[4] += w0 * vb0.x;  acc[5] += w0 * vb0.y;
            acc[6] += w0 * vb0.z;  acc[7] += w0 * vb0.w;
        }
    }

    const float inv = (wsum > 0.f) ? 1.f / wsum : 0.f;
    float* op = g_h[dt] + (size_t)node * DDIM + base;
    float4 o0 = make_float4(acc[0] * inv, acc[1] * inv, acc[2] * inv, acc[3] * inv);
    float4 o1 = make_float4(acc[4] * inv, acc[5] * inv, acc[6] * inv, acc[7] * inv);
    *(float4*)(op)     = o0;
    *(float4*)(op + 4) = o1;
}

// ======================= 4. split-bf16 HMMA GEMM (fp32 A, in-kernel split) =======
// Optional fused skip-mix epilogue: if mixF != null, C = alpha*(acc+bias) + (1-alpha)*mixF.
#define BM 128
#define BN 128
#define BK 64
#define LDS_STRIDE 72
#define AS_HI 0
#define AS_LO (AS_HI + BM * LDS_STRIDE * 2)
#define BS_HI (AS_LO + BM * LDS_STRIDE * 2)
#define BS_LO (BS_HI + BN * LDS_STRIDE * 2)
#define GEMM_SMEM (BS_LO + BN * LDS_STRIDE * 2)

__global__ __launch_bounds__(256) void hmma_gemm_kernel(
    const float* __restrict__ A, long strideA,
    const __nv_bfloat16* __restrict__ Bhi, const __nv_bfloat16* __restrict__ Blo, long strideB,
    const float* __restrict__ bias, long strideBias,
    float* __restrict__ C, long strideC,
    int M, int Ntot,
    const float* __restrict__ mixF, const float* __restrict__ skip)
{
    extern __shared__ char smem[];
    const uint32_t sbase = smem_u32(smem);

    const int tid = threadIdx.x;
    const int wid = tid >> 5, lane = tid & 31;
    const int t = blockIdx.z;
    const int m0 = blockIdx.x * BM;
    const int n0 = blockIdx.y * BN;
    const int mw = (wid & 1) * 64;
    const int nw = (wid >> 1) * 32;

    A += (size_t)t * strideA;
    Bhi += (size_t)t * strideB;  Blo += (size_t)t * strideB;
    bias += (size_t)t * strideBias;
    C += (size_t)t * strideC;

    float acc[4][4][4];
    #pragma unroll
    for (int i = 0; i < 4; ++i)
        #pragma unroll
        for (int j = 0; j < 4; ++j)
            #pragma unroll
            for (int r = 0; r < 4; ++r) acc[i][j][r] = 0.f;

    for (int kofs = 0; kofs < 256; kofs += BK) {
        __syncthreads();
        #pragma unroll
        for (int i = 0; i < 4; ++i) {
            int idx = tid + i * 256;
            int row = idx >> 3, c = (idx & 7) * 8;
            uint32_t soff = (uint32_t)(row * LDS_STRIDE + c) * 2;
            float4 v0 = make_float4(0.f, 0.f, 0.f, 0.f);
            float4 v1 = make_float4(0.f, 0.f, 0.f, 0.f);
            int gr = m0 + row;
            if (gr < M) {
                const float* ap = A + (size_t)gr * 256 + kofs + c;
                v0 = *(const float4*)ap;
                v1 = *(const float4*)(ap + 4);
            }
            uint4 hiq, loq;
            split8(v0, v1, hiq, loq);
            *(uint4*)(smem + AS_HI + soff) = hiq;
            *(uint4*)(smem + AS_LO + soff) = loq;
        }
        #pragma unroll
        for (int i = 0; i < 4; ++i) {
            int idx = tid + i * 256;
            int row = idx >> 3, c = (idx & 7) * 8;
            uint32_t soff = (uint32_t)(row * LDS_STRIDE + c) * 2;
            size_t s = (size_t)(n0 + row) * 256 + kofs + c;
            *(uint4*)(smem + BS_HI + soff) = *(const uint4*)(Bhi + s);
            *(uint4*)(smem + BS_LO + soff) = *(const uint4*)(Blo + s);
        }
        __syncthreads();

        #pragma unroll
        for (int kk = 0; kk < BK / 16; ++kk) {
            uint32_t a_hi[4][4], a_lo[4][4], b_hi[4][2], b_lo[4][2];
            #pragma unroll
            for (int i = 0; i < 4; ++i) {
                uint32_t off = (uint32_t)((mw + i * 16 + (lane & 15)) * LDS_STRIDE
                                          + kk * 16 + (lane >> 4) * 8) * 2;
                ldm_x4(a_hi[i], sbase + AS_HI + off);
                ldm_x4(a_lo[i], sbase + AS_LO + off);
            }
            // B fragments: one ldmatrix.x4 covers TWO adjacent n8 tiles (n16 x k16)
            // lanes 0-15 address rows of tile jp*2, lanes 16-31 rows of tile jp*2+1.
            #pragma unroll
            for (int jp = 0; jp < 2; ++jp) {
                uint32_t off = (uint32_t)((nw + jp * 16 + ((lane >> 4) << 3) + (lane & 7)) * LDS_STRIDE
                                          + kk * 16 + ((lane >> 3) & 1) * 8) * 2;
                uint32_t r4[4];
                ldm_x4(r4, sbase + BS_HI + off);
                b_hi[jp * 2][0] = r4[0];     b_hi[jp * 2][1] = r4[1];
                b_hi[jp * 2 + 1][0] = r4[2]; b_hi[jp * 2 + 1][1] = r4[3];
                ldm_x4(r4, sbase + BS_LO + off);
                b_lo[jp * 2][0] = r4[0];     b_lo[jp * 2][1] = r4[1];
                b_lo[jp * 2 + 1][0] = r4[2]; b_lo[jp * 2 + 1][1] = r4[3];
            }
            #pragma unroll
            for (int i = 0; i < 4; ++i)
                #pragma unroll
                for (int j = 0; j < 4; ++j) {
                    mma_bf16(acc[i][j], a_hi[i], b_hi[j]);
                    mma_bf16(acc[i][j], a_hi[i], b_lo[j]);
                    mma_bf16(acc[i][j], a_lo[i], b_hi[j]);
                }
        }
    }

    // epilogue: +bias, optional skip-mix with mixF
    const bool fuse = (mixF != nullptr);
    float alpha = 1.f, beta = 0.f;
    if (fuse) {
        alpha = 1.f / (1.f + expf(-skip[t]));
        beta = 1.f - alpha;
        mixF += (size_t)t * strideC;
    }
    #pragma unroll
    for (int i = 0; i < 4; ++i) {
        int r0 = m0 + mw + i * 16 + (lane >> 2);
        int r1 = r0 + 8;
        #pragma unroll
        for (int j = 0; j < 4; ++j) {
            int col = n0 + nw + j * 8 + (lane & 3) * 2;
            float b0 = bias[col], b1 = bias[col + 1];
            if (r0 < M) {
                float2 o = make_float2(acc[i][j][0] + b0, acc[i][j][1] + b1);
                if (fuse) {
                    const float2 f = *(const float2*)(mixF + (size_t)r0 * Ntot + col);
                    o.x = alpha * o.x + beta * f.x;
                    o.y = alpha * o.y + beta * f.y;
                }
                *(float2*)(C + (size_t)r0 * Ntot + col) = o;
            }
            if (r1 < M) {
                float2 o = make_float2(acc[i][j][2] + b0, acc[i][j][3] + b1);
                if (fuse) {
                    const float2 f = *(const float2*)(mixF + (size_t)r1 * Ntot + col);
                    o.x = alpha * o.x + beta * f.x;
                    o.y = alpha * o.y + beta * f.y;
                }
                *(float2*)(C + (size_t)r1 * Ntot + col) = o;
            }
        }
    }
}

// ======================= 5. LayerNorm (input already skip-mixed) =================
__global__ __launch_bounds__(256) void ln_kernel(
    const float* __restrict__ ln_w, const float* __restrict__ ln_b,
    float* __restrict__ out)
{
    long row = (long)blockIdx.x * 8 + (threadIdx.x >> 5);
    const int lane = threadIdx.x & 31;
    const int t = (int)(row / NNODE);

    const float* tr = (const float*)g_trans + row * DDIM + lane * 8;

    float v[8];
    float4 t0 = *(const float4*)(tr);
    float4 t1 = *(const float4*)(tr + 4);
    v[0] = t0.x; v[1] = t0.y; v[2] = t0.z; v[3] = t0.w;
    v[4] = t1.x; v[5] = t1.y; v[6] = t1.z; v[7] = t1.w;

    float sum = 0.f, sq = 0.f;
    #pragma unroll
    for (int j = 0; j < 8; ++j) { sum += v[j]; sq += v[j] * v[j]; }
    #pragma unroll
    for (int o = 16; o > 0; o >>= 1) {
        sum += __shfl_xor_sync(0xffffffffu, sum, o);
        sq  += __shfl_xor_sync(0xffffffffu, sq, o);
    }
    const float mean = sum * (1.f / 256.f);
    const float var  = sq * (1.f / 256.f) - mean * mean;
    const float rstd = rsqrtf(var + 1e-5f);

    const int cbase = t * 256 + lane * 8;
    float* op = out + row * DDIM + lane * 8;
    float4 o0, o1;
    o0.x = (v[0] - mean) * rstd * ln_w[cbase + 0] + ln_b[cbase + 0];
    o0.y = (v[1] - mean) * rstd * ln_w[cbase + 1] + ln_b[cbase + 1];
    o0.z = (v[2] - mean) * rstd * ln_w[cbase + 2] + ln_b[cbase + 2];
    o0.w = (v[3] - mean) * rstd * ln_w[cbase + 3] + ln_b[cbase + 3];
    o1.x = (v[4] - mean) * rstd * ln_w[cbase + 4] + ln_b[cbase + 4];
    o1.y = (v[5] - mean) * rstd * ln_w[cbase + 5] + ln_b[cbase + 5];
    o1.z = (v[6] - mean) * rstd * ln_w[cbase + 6] + ln_b[cbase + 6];
    o1.w = (v[7] - mean) * rstd * ln_w[cbase + 7] + ln_b[cbase + 7];
    *(float4*)(op)     = o0;
    *(float4*)(op + 4) = o1;
}

// ======================= host launch =============================================
extern "C" void kernel_launch(void* const* d_in, const int* in_sizes, int n_in,
                              void* d_out, int out_size)
{
    const float* feats = (const float*)d_in[0];
    const float* Wk    = (const float*)d_in[1];
    const float* bk    = (const float*)d_in[2];
    const float* Wq    = (const float*)d_in[3];
    const float* bq    = (const float*)d_in[4];
    const float* Wv    = (const float*)d_in[5];
    const float* bv    = (const float*)d_in[6];
    const float* Wa    = (const float*)d_in[7];
    const float* ba    = (const float*)d_in[8];
    const float* ln_w  = (const float*)d_in[9];
    const float* ln_b  = (const float*)d_in[10];
    const float* skip  = (const float*)d_in[11];
    const float* mu    = (const float*)d_in[12];
    const float* w_att = (const float*)d_in[13];
    const float* w_msg = (const float*)d_in[14];
    const int*   src   = (const int*)d_in[15];
    const int*   dst   = (const int*)d_in[16];
    float* out = (float*)d_out;

    static bool attr_done = false;
    if (!attr_done) {
        cudaFuncSetAttribute(hmma_gemm_kernel,
                             cudaFuncAttributeMaxDynamicSharedMemorySize, GEMM_SMEM);
        attr_done = true;
    }

    float *pbcat, *pQKV, *ph, *ptrans;
    __nv_bfloat16 *pWcH, *pWcL, *pWaH, *pWaL;
    cudaGetSymbolAddress((void**)&pbcat, g_bcat);
    cudaGetSymbolAddress((void**)&pQKV, g_QKV);
    cudaGetSymbolAddress((void**)&ph, g_h);
    cudaGetSymbolAddress((void**)&ptrans, g_trans);
    cudaGetSymbolAddress((void**)&pWcH, g_WcatT_hi);
    cudaGetSymbolAddress((void**)&pWcL, g_WcatT_lo);
    cudaGetSymbolAddress((void**)&pWaH, g_WaT_hi);
    cudaGetSymbolAddress((void**)&pWaL, g_WaT_lo);

    // 1. weight prep
    {
        dim3 grid(1024, 2);
        prep_kernel<<<grid, 256>>>(Wk, bk, Wq, bq, Wv, bv, Wa, w_att, w_msg);
    }

    // 2. CSR build (multi-block scan)
    zerodeg_kernel<<<(2 * NNODE + 255) / 256, 256>>>();
    {
        dim3 grid((EE + 255) / 256, 2);
        hist_kernel<<<grid, 256>>>(dst);
    }
    {
        dim3 grid(NSCB, 2);
        scanA_kernel<<<grid, SCB>>>();
    }
    scanB_kernel<<<2, 128>>>();
    {
        dim3 grid(NSCB, 2);
        scanC_kernel<<<grid, SCB>>>();
    }
    {
        dim3 grid((EE + 255) / 256, 2);
        scatter_kernel<<<grid, 256>>>(src, dst);
    }

    // 3. QKV projection (HMMA, fp32 A = feats directly)
    {
        dim3 grid((NNODE + BM - 1) / BM, QKVW / BN, 2);
        hmma_gemm_kernel<<<grid, 256, GEMM_SMEM>>>(
            feats, (long)NNODE * DDIM,
            pWcH, pWcL, (long)QKVW * DDIM,
            pbcat, (long)QKVW,
            pQKV, (long)NNODE * QKVW,
            NNODE, QKVW,
            nullptr, nullptr);
    }

    // 4. aggregation
    {
        dim3 grid((NNODE + 7) / 8, 2);
        agg_kernel<<<grid, 256>>>(mu);
    }

    // 5. output projection + fused skip-mix (HMMA, fp32 A = g_h)
    {
        dim3 grid((NNODE + BM - 1) / BM, DDIM / BN, 2);
        hmma_gemm_kernel<<<grid, 256, GEMM_SMEM>>>(
            ph, (long)NNODE * DDIM,
            pWaH, pWaL, (long)DDIM * DDIM,
            ba, (long)DDIM,
            ptrans, (long)NNODE * DDIM,
            NNODE, DDIM,
            feats, skip);
    }

    // 6. LayerNorm -> d_out
    ln_kernel<<<(2 * NNODE) / 8, 256>>>(ln_w, ln_b, out);
}

// round 13
// speedup vs baseline: 1.0426x; 1.0426x over previous
#include <cuda_runtime.h>
#include <cuda_bf16.h>
#include <math.h>
#include <stdint.h>

#define NNODE 50000
#define DDIM  256
#define HH    8
#define EE    500000
#define QKVW  768
#define ATT_SCALE 0.17677669529663687f  // 1/sqrt(32)

#define SCB   512                       // scan elements per block
#define NSCB  ((NNODE + SCB - 1) / SCB) // 98

// ======================= device scratch ==========================================
__device__ float g_bcat[2][QKVW];
__device__ __nv_bfloat16 g_WcatT_hi[2][(size_t)QKVW * DDIM];  // [n][k], n = Q|K'|V'
__device__ __nv_bfloat16 g_WcatT_lo[2][(size_t)QKVW * DDIM];
__device__ __nv_bfloat16 g_WaT_hi[2][(size_t)DDIM * DDIM];
__device__ __nv_bfloat16 g_WaT_lo[2][(size_t)DDIM * DDIM];
__device__ float g_QKV[2][(size_t)NNODE * QKVW];  // fp32: Q(256)|K'(256)|V'(256)
__device__ float g_h[2][(size_t)NNODE * DDIM];    // fp32 aggregated messages
__device__ float g_trans[2][(size_t)NNODE * DDIM];
// CSR-by-destination scratch
__device__ int g_deg[2][NNODE];
__device__ int g_rows[2][NNODE + 1];
__device__ int g_cursor[2][NNODE];
__device__ int g_esrc[2][EE];
__device__ int g_bsum[2][NSCB];
__device__ int g_boff[2][NSCB];

// ======================= PTX helpers (base-target safe) ==========================
__device__ __forceinline__ uint32_t smem_u32(const void* p) {
    uint32_t a;
    asm("{ .reg .u64 t; cvta.to.shared.u64 t, %1; cvt.u32.u64 %0, t; }" : "=r"(a) : "l"(p));
    return a;
}
__device__ __forceinline__ void ldm_x4(uint32_t* r, uint32_t addr) {
    asm volatile("ldmatrix.sync.aligned.m8n8.x4.shared.b16 {%0,%1,%2,%3}, [%4];"
                 : "=r"(r[0]), "=r"(r[1]), "=r"(r[2]), "=r"(r[3]) : "r"(addr));
}
__device__ __forceinline__ void ldm_x2(uint32_t* r, uint32_t addr) {
    asm volatile("ldmatrix.sync.aligned.m8n8.x2.shared.b16 {%0,%1}, [%2];"
                 : "=r"(r[0]), "=r"(r[1]) : "r"(addr));
}
__device__ __forceinline__ void mma_bf16(float* c, const uint32_t* a, const uint32_t* b) {
    asm volatile("mma.sync.aligned.m16n8k16.row.col.f32.bf16.bf16.f32 "
                 "{%0,%1,%2,%3}, {%4,%5,%6,%7}, {%8,%9}, {%0,%1,%2,%3};"
                 : "+f"(c[0]), "+f"(c[1]), "+f"(c[2]), "+f"(c[3])
                 : "r"(a[0]), "r"(a[1]), "r"(a[2]), "r"(a[3]), "r"(b[0]), "r"(b[1]));
}

// split 8 fp32 into bf16 hi/lo packed uint4s
__device__ __forceinline__ void split8(const float4& v0, const float4& v1,
                                       uint4& hiq, uint4& loq) {
    float f[8] = {v0.x, v0.y, v0.z, v0.w, v1.x, v1.y, v1.z, v1.w};
    __nv_bfloat162 hh[4], ll[4];
    #pragma unroll
    for (int j = 0; j < 4; ++j) {
        __nv_bfloat16 h0 = __float2bfloat16(f[2 * j]);
        __nv_bfloat16 h1 = __float2bfloat16(f[2 * j + 1]);
        __nv_bfloat16 l0 = __float2bfloat16(f[2 * j]     - __bfloat162float(h0));
        __nv_bfloat16 l1 = __float2bfloat16(f[2 * j + 1] - __bfloat162float(h1));
        hh[j] = __halves2bfloat162(h0, h1);
        ll[j] = __halves2bfloat162(l0, l1);
    }
    hiq = *(const uint4*)hh;
    loq = *(const uint4*)ll;
}

// ======================= 1. prep: fold + transpose + bf16 split ==================
__global__ __launch_bounds__(256) void prep_kernel(
    const float* __restrict__ Wk, const float* __restrict__ bk,
    const float* __restrict__ Wq, const float* __restrict__ bq,
    const float* __restrict__ Wv, const float* __restrict__ bv,
    const float* __restrict__ Wa,
    const float* __restrict__ w_att, const float* __restrict__ w_msg)
{
    const int t = blockIdx.y;
    const int n = blockIdx.x;
    const int k = threadIdx.x;

    float val;
    if (n < 768) {
        if (n < 256) {
            val = Wq[((size_t)t * 256 + k) * 256 + n];
        } else {
            const int j = (n - 256) & 255;
            const int h = j >> 5, jj = j & 31;
            const float* W = (n < 512) ? Wk : Wv;
            const float* wm = ((n < 512) ? w_att : w_msg) + ((size_t)(t * 8 + h)) * 1024 + jj;
            const float* wrow = W + ((size_t)t * 256 + k) * 256 + h * 32;
            float a = 0.f;
            #pragma unroll 8
            for (int i = 0; i < 32; ++i) a += wrow[i] * wm[i * 32];
            val = a;
        }
        __nv_bfloat16 hi = __float2bfloat16(val);
        __nv_bfloat16 lo = __float2bfloat16(val - __bfloat162float(hi));
        g_WcatT_hi[t][(size_t)n * 256 + k] = hi;
        g_WcatT_lo[t][(size_t)n * 256 + k] = lo;
        if (k == 0) {
            float b;
            if (n < 256) b = bq[t * 256 + n];
            else {
                const int j = (n - 256) & 255;
                const int h = j >> 5, jj = j & 31;
                const float* bb = (n < 512) ? bk : bv;
                const float* wm = ((n < 512) ? w_att : w_msg) + ((size_t)(t * 8 + h)) * 1024 + jj;
                float a = 0.f;
                #pragma unroll 8
                for (int i = 0; i < 32; ++i) a += bb[t * 256 + h * 32 + i] * wm[i * 32];
                b = a;
            }
            g_bcat[t][n] = b;
        }
    } else {
        const int nn = n - 768;
        val = Wa[((size_t)t * 256 + k) * 256 + nn];
        __nv_bfloat16 hi = __float2bfloat16(val);
        __nv_bfloat16 lo = __float2bfloat16(val - __bfloat162float(hi));
        g_WaT_hi[t][(size_t)nn * 256 + k] = hi;
        g_WaT_lo[t][(size_t)nn * 256 + k] = lo;
    }
}

// ======================= 2. CSR build ============================================
__global__ void zerodeg_kernel()
{
    int i = blockIdx.x * blockDim.x + threadIdx.x;
    if (i < 2 * NNODE) ((int*)g_deg)[i] = 0;
}

__global__ void hist_kernel(const int* __restrict__ dst)
{
    const int et = blockIdx.y;
    int e = blockIdx.x * blockDim.x + threadIdx.x;
    if (e >= EE) return;
    atomicAdd(&g_deg[et][dst[(long)et * EE + e]], 1);
}

// phase A: per-block exclusive scan of 512 degs; local offsets + block totals
__global__ __launch_bounds__(SCB) void scanA_kernel()
{
    const int et = blockIdx.y;
    const int b = blockIdx.x;
    const int tid = threadIdx.x;
    const int idx = b * SCB + tid;
    const int lane = tid & 31, w = tid >> 5;

    int d = (idx < NNODE) ? g_deg[et][idx] : 0;
    int x = d;
    #pragma unroll
    for (int o = 1; o < 32; o <<= 1) {
        int n = __shfl_up_sync(0xffffffffu, x, o);
        if (lane >= o) x += n;
    }
    __shared__ int ws[SCB / 32];
    if (lane == 31) ws[w] = x;
    __syncthreads();
    if (w == 0) {
        int y = (lane < SCB / 32) ? ws[lane] : 0;
        #pragma unroll
        for (int o = 1; o < SCB / 32; o <<= 1) {
            int n = __shfl_up_sync(0xffffffffu, y, o);
            if (lane >= o) y += n;
        }
        if (lane < SCB / 32) ws[lane] = y;
    }
    __syncthreads();
    const int incl = x + (w > 0 ? ws[w - 1] : 0);
    if (idx < NNODE) g_rows[et][idx] = incl - d;
    if (tid == SCB - 1) g_bsum[et][b] = incl;
}

// phase B: scan the NSCB block totals (one block per etype)
__global__ __launch_bounds__(128) void scanB_kernel()
{
    const int et = blockIdx.x;
    const int t = threadIdx.x;
    const int lane = t & 31, w = t >> 5;
    int v = (t < NSCB) ? g_bsum[et][t] : 0;
    int x = v;
    #pragma unroll
    for (int o = 1; o < 32; o <<= 1) {
        int n = __shfl_up_sync(0xffffffffu, x, o);
        if (lane >= o) x += n;
    }
    __shared__ int ws[4];
    if (lane == 31) ws[w] = x;
    __syncthreads();
    int add = 0;
    #pragma unroll
    for (int i = 0; i < 4; ++i) if (i < w) add += ws[i];
    const int incl = x + add;
    if (t < NSCB) g_boff[et][t] = incl - v;
    if (t == NSCB - 1) g_rows[et][NNODE] = incl;
}

// phase C: add block offsets; emit rows + cursor
__global__ __launch_bounds__(SCB) void scanC_kernel()
{
    const int et = blockIdx.y;
    const int b = blockIdx.x;
    const int idx = b * SCB + threadIdx.x;
    if (idx >= NNODE) return;
    const int r = g_rows[et][idx] + g_boff[et][b];
    g_rows[et][idx] = r;
    g_cursor[et][idx] = r;
}

__global__ void scatter_kernel(const int* __restrict__ src, const int* __restrict__ dst)
{
    const int et = blockIdx.y;
    int e = blockIdx.x * blockDim.x + threadIdx.x;
    if (e >= EE) return;
    int s = src[(long)et * EE + e];
    int d = dst[(long)et * EE + e];
    int pos = atomicAdd(&g_cursor[et][d], 1);
    g_esrc[et][pos] = s;
}

// ======================= 3. warp-per-dst aggregation (2-edge unroll) ==============
__device__ __forceinline__ float dot8(const float4& qa, const float4& qb,
                                      const float4& ka, const float4& kb) {
    return qa.x * ka.x + qa.y * ka.y + qa.z * ka.z + qa.w * ka.w
         + qb.x * kb.x + qb.y * kb.y + qb.z * kb.z + qb.w * kb.w;
}

__global__ __launch_bounds__(256) void agg_kernel(const float* __restrict__ mu)
{
    const int et = blockIdx.y;
    const int dt = 1 - et;
    const int warp = threadIdx.x >> 5;
    const int lane = threadIdx.x & 31;
    const int node = blockIdx.x * 8 + warp;
    if (node >= NNODE) return;

    const int r0 = g_rows[et][node];
    const int r1 = g_rows[et][node + 1];

    const int h = lane >> 2;
    const int base = lane * 8;
    const float muh = mu[et * 8 + h] * ATT_SCALE;

    float acc[8];
    #pragma unroll
    for (int j = 0; j < 8; ++j) acc[j] = 0.f;
    float wsum = 0.f;

    if (r0 < r1) {
        const float* qrow = g_QKV[dt] + (size_t)node * QKVW + base;
        const float4 qa = *(const float4*)qrow;
        const float4 qb = *(const float4*)(qrow + 4);
        const int* __restrict__ ep = g_esrc[et];
        const float* __restrict__ kvbase = g_QKV[et];

        int j = r0;
        for (; j + 1 < r1; j += 2) {
            const int s0 = ep[j];
            const int s1 = ep[j + 1];
            const float* kr0 = kvbase + (size_t)s0 * QKVW + 256 + base;
            const float* kr1 = kvbase + (size_t)s1 * QKVW + 256 + base;
            float4 ka0 = *(const float4*)kr0;
            float4 kb0 = *(const float4*)(kr0 + 4);
            float4 va0 = *(const float4*)(kr0 + 256);
            float4 vb0 = *(const float4*)(kr0 + 260);
            float4 ka1 = *(const float4*)kr1;
            float4 kb1 = *(const float4*)(kr1 + 4);
            float4 va1 = *(const float4*)(kr1 + 256);
            float4 vb1 = *(const float4*)(kr1 + 260);

            float p0 = dot8(qa, qb, ka0, kb0);
            float p1 = dot8(qa, qb, ka1, kb1);
            p0 += __shfl_xor_sync(0xffffffffu, p0, 1);
            p1 += __shfl_xor_sync(0xffffffffu, p1, 1);
            p0 += __shfl_xor_sync(0xffffffffu, p0, 2);
            p1 += __shfl_xor_sync(0xffffffffu, p1, 2);

            float w0 = __expf(p0 * muh);
            float w1 = __expf(p1 * muh);
            wsum += w0 + w1;
            acc[0] += w0 * va0.x + w1 * va1.x;
            acc[1] += w0 * va0.y + w1 * va1.y;
            acc[2] += w0 * va0.z + w1 * va1.z;
            acc[3] += w0 * va0.w + w1 * va1.w;
            acc[4] += w0 * vb0.x + w1 * vb1.x;
            acc[5] += w0 * vb0.y + w1 * vb1.y;
            acc[6] += w0 * vb0.z + w1 * vb1.z;
            acc[7] += w0 * vb0.w + w1 * vb1.w;
        }
        if (j < r1) {
            const int s0 = ep[j];
            const float* kr0 = kvbase + (size_t)s0 * QKVW + 256 + base;
            float4 ka0 = *(const float4*)kr0;
            float4 kb0 = *(const float4*)(kr0 + 4);
            float4 va0 = *(const float4*)(kr0 + 256);
            float4 vb0 = *(const float4*)(kr0 + 260);
            float p0 = dot8(qa, qb, ka0, kb0);
            p0 += __shfl_xor_sync(0xffffffffu, p0, 1);
            p0 += __shfl_xor_sync(0xffffffffu, p0, 2);
            float w0 = __expf(p0 * muh);
            wsum += w0;
            acc[0] += w0 * va0.x;  acc[1] += w0 * va0.y;
            acc[2] += w0 * va0.z;  acc[3] += w0 * va0.w;
            acc[4] += w0 * vb0.x;  acc[5] += w0 * vb0.y;
            acc[6] += w0 * vb0.z;  acc[7] += w0 * vb0.w;
        }
    }

    const float inv = (wsum > 0.f) ? 1.f / wsum : 0.f;
    float* op = g_h[dt] + (size_t)node * DDIM + base;
    float4 o0 = make_float4(acc[0] * inv, acc[1] * inv, acc[2] * inv, acc[3] * inv);
    float4 o1 = make_float4(acc[4] * inv, acc[5] * inv, acc[6] * inv, acc[7] * inv);
    *(float4*)(op)     = o0;
    *(float4*)(op + 4) = o1;
}

// ======================= 4. split-bf16 HMMA GEMM (fp32 A, in-kernel split) =======
#define BM 128
#define BN 128
#define BK 64
#define LDS_STRIDE 72
#define AS_HI 0
#define AS_LO (AS_HI + BM * LDS_STRIDE * 2)
#define BS_HI (AS_LO + BM * LDS_STRIDE * 2)
#define BS_LO (BS_HI + BN * LDS_STRIDE * 2)
#define GEMM_SMEM (BS_LO + BN * LDS_STRIDE * 2)

__global__ __launch_bounds__(256) void hmma_gemm_kernel(
    const float* __restrict__ A, long strideA,
    const __nv_bfloat16* __restrict__ Bhi, const __nv_bfloat16* __restrict__ Blo, long strideB,
    const float* __restrict__ bias, long strideBias,
    float* __restrict__ C, long strideC,
    int M, int Ntot)
{
    extern __shared__ char smem[];
    const uint32_t sbase = smem_u32(smem);

    const int tid = threadIdx.x;
    const int wid = tid >> 5, lane = tid & 31;
    const int t = blockIdx.z;
    const int m0 = blockIdx.x * BM;
    const int n0 = blockIdx.y * BN;
    const int mw = (wid & 1) * 64;
    const int nw = (wid >> 1) * 32;

    A += (size_t)t * strideA;
    Bhi += (size_t)t * strideB;  Blo += (size_t)t * strideB;
    bias += (size_t)t * strideBias;
    C += (size_t)t * strideC;

    float acc[4][4][4];
    #pragma unroll
    for (int i = 0; i < 4; ++i)
        #pragma unroll
        for (int j = 0; j < 4; ++j)
            #pragma unroll
            for (int r = 0; r < 4; ++r) acc[i][j][r] = 0.f;

    for (int kofs = 0; kofs < 256; kofs += BK) {
        __syncthreads();
        #pragma unroll
        for (int i = 0; i < 4; ++i) {
            int idx = tid + i * 256;
            int row = idx >> 3, c = (idx & 7) * 8;
            uint32_t soff = (uint32_t)(row * LDS_STRIDE + c) * 2;
            float4 v0 = make_float4(0.f, 0.f, 0.f, 0.f);
            float4 v1 = make_float4(0.f, 0.f, 0.f, 0.f);
            int gr = m0 + row;
            if (gr < M) {
                const float* ap = A + (size_t)gr * 256 + kofs + c;
                v0 = *(const float4*)ap;
                v1 = *(const float4*)(ap + 4);
            }
            uint4 hiq, loq;
            split8(v0, v1, hiq, loq);
            *(uint4*)(smem + AS_HI + soff) = hiq;
            *(uint4*)(smem + AS_LO + soff) = loq;
        }
        #pragma unroll
        for (int i = 0; i < 4; ++i) {
            int idx = tid + i * 256;
            int row = idx >> 3, c = (idx & 7) * 8;
            uint32_t soff = (uint32_t)(row * LDS_STRIDE + c) * 2;
            size_t s = (size_t)(n0 + row) * 256 + kofs + c;
            *(uint4*)(smem + BS_HI + soff) = *(const uint4*)(Bhi + s);
            *(uint4*)(smem + BS_LO + soff) = *(const uint4*)(Blo + s);
        }
        __syncthreads();

        #pragma unroll
        for (int kk = 0; kk < BK / 16; ++kk) {
            uint32_t a_hi[4][4], a_lo[4][4], b_hi[4][2], b_lo[4][2];
            #pragma unroll
            for (int i = 0; i < 4; ++i) {
                uint32_t off = (uint32_t)((mw + i * 16 + (lane & 15)) * LDS_STRIDE
                                          + kk * 16 + (lane >> 4) * 8) * 2;
                ldm_x4(a_hi[i], sbase + AS_HI + off);
                ldm_x4(a_lo[i], sbase + AS_LO + off);
            }
            #pragma unroll
            for (int j = 0; j < 4; ++j) {
                uint32_t off = (uint32_t)((nw + j * 8 + (lane & 7)) * LDS_STRIDE
                                          + kk * 16 + ((lane >> 3) & 1) * 8) * 2;
                ldm_x2(b_hi[j], sbase + BS_HI + off);
                ldm_x2(b_lo[j], sbase + BS_LO + off);
            }
            #pragma unroll
            for (int i = 0; i < 4; ++i)
                #pragma unroll
                for (int j = 0; j < 4; ++j) {
                    mma_bf16(acc[i][j], a_hi[i], b_hi[j]);
                    mma_bf16(acc[i][j], a_hi[i], b_lo[j]);
                    mma_bf16(acc[i][j], a_lo[i], b_hi[j]);
                }
        }
    }

    #pragma unroll
    for (int i = 0; i < 4; ++i) {
        int r0 = m0 + mw + i * 16 + (lane >> 2);
        int r1 = r0 + 8;
        #pragma unroll
        for (int j = 0; j < 4; ++j) {
            int col = n0 + nw + j * 8 + (lane & 3) * 2;
            float b0 = bias[col], b1 = bias[col + 1];
            if (r0 < M) {
                float2 o = make_float2(acc[i][j][0] + b0, acc[i][j][1] + b1);
                *(float2*)(C + (size_t)r0 * Ntot + col) = o;
            }
            if (r1 < M) {
                float2 o = make_float2(acc[i][j][2] + b0, acc[i][j][3] + b1);
                *(float2*)(C + (size_t)r1 * Ntot + col) = o;
            }
        }
    }
}

// ======================= 5. skip-mix + LayerNorm =================================
__global__ __launch_bounds__(256) void ln_kernel(
    const float* __restrict__ feats, const float* __restrict__ skip,
    const float* __restrict__ ln_w, const float* __restrict__ ln_b,
    float* __restrict__ out)
{
    long row = (long)blockIdx.x * 8 + (threadIdx.x >> 5);
    const int lane = threadIdx.x & 31;
    const int t = (int)(row / NNODE);
    const float alpha = 1.f / (1.f + expf(-skip[t]));
    const float beta = 1.f - alpha;

    const float* tr = (const float*)g_trans + row * DDIM + lane * 8;
    const float* ft = feats + row * DDIM + lane * 8;

    float v[8];
    float4 t0 = *(const float4*)(tr);
    float4 t1 = *(const float4*)(tr + 4);
    float4 f0 = *(const float4*)(ft);
    float4 f1 = *(const float4*)(ft + 4);
    v[0] = alpha * t0.x + beta * f0.x;  v[1] = alpha * t0.y + beta * f0.y;
    v[2] = alpha * t0.z + beta * f0.z;  v[3] = alpha * t0.w + beta * f0.w;
    v[4] = alpha * t1.x + beta * f1.x;  v[5] = alpha * t1.y + beta * f1.y;
    v[6] = alpha * t1.z + beta * f1.z;  v[7] = alpha * t1.w + beta * f1.w;

    float sum = 0.f, sq = 0.f;
    #pragma unroll
    for (int j = 0; j < 8; ++j) { sum += v[j]; sq += v[j] * v[j]; }
    #pragma unroll
    for (int o = 16; o > 0; o >>= 1) {
        sum += __shfl_xor_sync(0xffffffffu, sum, o);
        sq  += __shfl_xor_sync(0xffffffffu, sq, o);
    }
    const float mean = sum * (1.f / 256.f);
    const float var  = sq * (1.f / 256.f) - mean * mean;
    const float rstd = rsqrtf(var + 1e-5f);

    const int cbase = t * 256 + lane * 8;
    float* op = out + row * DDIM + lane * 8;
    float4 o0, o1;
    o0.x = (v[0] - mean) * rstd * ln_w[cbase + 0] + ln_b[cbase + 0];
    o0.y = (v[1] - mean) * rstd * ln_w[cbase + 1] + ln_b[cbase + 1];
    o0.z = (v[2] - mean) * rstd * ln_w[cbase + 2] + ln_b[cbase + 2];
    o0.w = (v[3] - mean) * rstd * ln_w[cbase + 3] + ln_b[cbase + 3];
    o1.x = (v[4] - mean) * rstd * ln_w[cbase + 4] + ln_b[cbase + 4];
    o1.y = (v[5] - mean) * rstd * ln_w[cbase + 5] + ln_b[cbase + 5];
    o1.z = (v[6] - mean) * rstd * ln_w[cbase + 6] + ln_b[cbase + 6];
    o1.w = (v[7] - mean) * rstd * ln_w[cbase + 7] + ln_b[cbase + 7];
    *(float4*)(op)     = o0;
    *(float4*)(op + 4) = o1;
}

// ======================= host launch =============================================
extern "C" void kernel_launch(void* const* d_in, const int* in_sizes, int n_in,
                              void* d_out, int out_size)
{
    const float* feats = (const float*)d_in[0];
    const float* Wk    = (const float*)d_in[1];
    const float* bk    = (const float*)d_in[2];
    const float* Wq    = (const float*)d_in[3];
    const float* bq    = (const float*)d_in[4];
    const float* Wv    = (const float*)d_in[5];
    const float* bv    = (const float*)d_in[6];
    const float* Wa    = (const float*)d_in[7];
    const float* ba    = (const float*)d_in[8];
    const float* ln_w  = (const float*)d_in[9];
    const float* ln_b  = (const float*)d_in[10];
    const float* skip  = (const float*)d_in[11];
    const float* mu    = (const float*)d_in[12];
    const float* w_att = (const float*)d_in[13];
    const float* w_msg = (const float*)d_in[14];
    const int*   src   = (const int*)d_in[15];
    const int*   dst   = (const int*)d_in[16];
    float* out = (float*)d_out;

    static bool attr_done = false;
    if (!attr_done) {
        cudaFuncSetAttribute(hmma_gemm_kernel,
                             cudaFuncAttributeMaxDynamicSharedMemorySize, GEMM_SMEM);
        attr_done = true;
    }

    float *pbcat, *pQKV, *ph, *ptrans;
    __nv_bfloat16 *pWcH, *pWcL, *pWaH, *pWaL;
    cudaGetSymbolAddress((void**)&pbcat, g_bcat);
    cudaGetSymbolAddress((void**)&pQKV, g_QKV);
    cudaGetSymbolAddress((void**)&ph, g_h);
    cudaGetSymbolAddress((void**)&ptrans, g_trans);
    cudaGetSymbolAddress((void**)&pWcH, g_WcatT_hi);
    cudaGetSymbolAddress((void**)&pWcL, g_WcatT_lo);
    cudaGetSymbolAddress((void**)&pWaH, g_WaT_hi);
    cudaGetSymbolAddress((void**)&pWaL, g_WaT_lo);

    // 1. weight prep
    {
        dim3 grid(1024, 2);
        prep_kernel<<<grid, 256>>>(Wk, bk, Wq, bq, Wv, bv, Wa, w_att, w_msg);
    }

    // 2. CSR build (multi-block scan)
    zerodeg_kernel<<<(2 * NNODE + 255) / 256, 256>>>();
    {
        dim3 grid((EE + 255) / 256, 2);
        hist_kernel<<<grid, 256>>>(dst);
    }
    {
        dim3 grid(NSCB, 2);
        scanA_kernel<<<grid, SCB>>>();
    }
    scanB_kernel<<<2, 128>>>();
    {
        dim3 grid(NSCB, 2);
        scanC_kernel<<<grid, SCB>>>();
    }
    {
        dim3 grid((EE + 255) / 256, 2);
        scatter_kernel<<<grid, 256>>>(src, dst);
    }

    // 3. QKV projection (HMMA, fp32 A = feats directly)
    {
        dim3 grid((NNODE + BM - 1) / BM, QKVW / BN, 2);
        hmma_gemm_kernel<<<grid, 256, GEMM_SMEM>>>(
            feats, (long)NNODE * DDIM,
            pWcH, pWcL, (long)QKVW * DDIM,
            pbcat, (long)QKVW,
            pQKV, (long)NNODE * QKVW,
            NNODE, QKVW);
    }

    // 4. aggregation
    {
        dim3 grid((NNODE + 7) / 8, 2);
        agg_kernel<<<grid, 256>>>(mu);
    }

    // 5. output projection (HMMA, fp32 A = g_h)
    {
        dim3 grid((NNODE + BM - 1) / BM, DDIM / BN, 2);
        hmma_gemm_kernel<<<grid, 256, GEMM_SMEM>>>(
            ph, (long)NNODE * DDIM,
            pWaH, pWaL, (long)DDIM * DDIM,
            ba, (long)DDIM,
            ptrans, (long)NNODE * DDIM,
            NNODE, DDIM);
    }

    // 6. skip-mix + LayerNorm -> d_out
    ln_kernel<<<(2 * NNODE) / 8, 256>>>(feats, skip, ln_w, ln_b, out);
}

// round 14
// speedup vs baseline: 1.0495x; 1.0066x over previous
#include <cuda_runtime.h>
#include <cuda_bf16.h>
#include <math.h>
#include <stdint.h>

#define NNODE 50000
#define DDIM  256
#define HH    8
#define EE    500000
#define QKVW  768
#define ATT_SCALE 0.17677669529663687f  // 1/sqrt(32)

#define SCB   512                       // scan elements per block
#define NSCB  ((NNODE + SCB - 1) / SCB) // 98

// ======================= device scratch ==========================================
__device__ float g_bcat[2][QKVW];
__device__ __nv_bfloat16 g_WcatT_hi[2][(size_t)QKVW * DDIM];  // [n][k], n = Q|K'|V'
__device__ __nv_bfloat16 g_WcatT_lo[2][(size_t)QKVW * DDIM];
__device__ __nv_bfloat16 g_WaT_hi[2][(size_t)DDIM * DDIM];
__device__ __nv_bfloat16 g_WaT_lo[2][(size_t)DDIM * DDIM];
__device__ float g_QKV[2][(size_t)NNODE * QKVW];  // fp32: Q(256)|K'(256)|V'(256)
__device__ float g_h[2][(size_t)NNODE * DDIM];    // fp32 aggregated messages
__device__ float g_trans[2][(size_t)NNODE * DDIM];
// CSR-by-destination scratch
__device__ int g_deg[2][NNODE];
__device__ int g_rows[2][NNODE + 1];
__device__ int g_cursor[2][NNODE];
__device__ int g_esrc[2][EE];
__device__ int g_bsum[2][NSCB];
__device__ int g_boff[2][NSCB];

// ======================= PTX helpers (base-target safe) ==========================
__device__ __forceinline__ uint32_t smem_u32(const void* p) {
    uint32_t a;
    asm("{ .reg .u64 t; cvta.to.shared.u64 t, %1; cvt.u32.u64 %0, t; }" : "=r"(a) : "l"(p));
    return a;
}
__device__ __forceinline__ void ldm_x4(uint32_t* r, uint32_t addr) {
    asm volatile("ldmatrix.sync.aligned.m8n8.x4.shared.b16 {%0,%1,%2,%3}, [%4];"
                 : "=r"(r[0]), "=r"(r[1]), "=r"(r[2]), "=r"(r[3]) : "r"(addr));
}
__device__ __forceinline__ void ldm_x2(uint32_t* r, uint32_t addr) {
    asm volatile("ldmatrix.sync.aligned.m8n8.x2.shared.b16 {%0,%1}, [%2];"
                 : "=r"(r[0]), "=r"(r[1]) : "r"(addr));
}
__device__ __forceinline__ void mma_bf16(float* c, const uint32_t* a, const uint32_t* b) {
    asm volatile("mma.sync.aligned.m16n8k16.row.col.f32.bf16.bf16.f32 "
                 "{%0,%1,%2,%3}, {%4,%5,%6,%7}, {%8,%9}, {%0,%1,%2,%3};"
                 : "+f"(c[0]), "+f"(c[1]), "+f"(c[2]), "+f"(c[3])
                 : "r"(a[0]), "r"(a[1]), "r"(a[2]), "r"(a[3]), "r"(b[0]), "r"(b[1]));
}

// split 8 fp32 into bf16 hi/lo packed uint4s
__device__ __forceinline__ void split8(const float4& v0, const float4& v1,
                                       uint4& hiq, uint4& loq) {
    float f[8] = {v0.x, v0.y, v0.z, v0.w, v1.x, v1.y, v1.z, v1.w};
    __nv_bfloat162 hh[4], ll[4];
    #pragma unroll
    for (int j = 0; j < 4; ++j) {
        __nv_bfloat16 h0 = __float2bfloat16(f[2 * j]);
        __nv_bfloat16 h1 = __float2bfloat16(f[2 * j + 1]);
        __nv_bfloat16 l0 = __float2bfloat16(f[2 * j]     - __bfloat162float(h0));
        __nv_bfloat16 l1 = __float2bfloat16(f[2 * j + 1] - __bfloat162float(h1));
        hh[j] = __halves2bfloat162(h0, h1);
        ll[j] = __halves2bfloat162(l0, l1);
    }
    hiq = *(const uint4*)hh;
    loq = *(const uint4*)ll;
}

// ======================= 1. prep: fold + transpose + bf16 split ==================
__global__ __launch_bounds__(256) void prep_kernel(
    const float* __restrict__ Wk, const float* __restrict__ bk,
    const float* __restrict__ Wq, const float* __restrict__ bq,
    const float* __restrict__ Wv, const float* __restrict__ bv,
    const float* __restrict__ Wa,
    const float* __restrict__ w_att, const float* __restrict__ w_msg)
{
    const int t = blockIdx.y;
    const int n = blockIdx.x;
    const int k = threadIdx.x;

    float val;
    if (n < 768) {
        if (n < 256) {
            val = Wq[((size_t)t * 256 + k) * 256 + n];
        } else {
            const int j = (n - 256) & 255;
            const int h = j >> 5, jj = j & 31;
            const float* W = (n < 512) ? Wk : Wv;
            const float* wm = ((n < 512) ? w_att : w_msg) + ((size_t)(t * 8 + h)) * 1024 + jj;
            const float* wrow = W + ((size_t)t * 256 + k) * 256 + h * 32;
            float a = 0.f;
            #pragma unroll 8
            for (int i = 0; i < 32; ++i) a += wrow[i] * wm[i * 32];
            val = a;
        }
        __nv_bfloat16 hi = __float2bfloat16(val);
        __nv_bfloat16 lo = __float2bfloat16(val - __bfloat162float(hi));
        g_WcatT_hi[t][(size_t)n * 256 + k] = hi;
        g_WcatT_lo[t][(size_t)n * 256 + k] = lo;
        if (k == 0) {
            float b;
            if (n < 256) b = bq[t * 256 + n];
            else {
                const int j = (n - 256) & 255;
                const int h = j >> 5, jj = j & 31;
                const float* bb = (n < 512) ? bk : bv;
                const float* wm = ((n < 512) ? w_att : w_msg) + ((size_t)(t * 8 + h)) * 1024 + jj;
                float a = 0.f;
                #pragma unroll 8
                for (int i = 0; i < 32; ++i) a += bb[t * 256 + h * 32 + i] * wm[i * 32];
                b = a;
            }
            g_bcat[t][n] = b;
        }
    } else {
        const int nn = n - 768;
        val = Wa[((size_t)t * 256 + k) * 256 + nn];
        __nv_bfloat16 hi = __float2bfloat16(val);
        __nv_bfloat16 lo = __float2bfloat16(val - __bfloat162float(hi));
        g_WaT_hi[t][(size_t)nn * 256 + k] = hi;
        g_WaT_lo[t][(size_t)nn * 256 + k] = lo;
    }
}

// ======================= 2. CSR build ============================================
__global__ void zerodeg_kernel()
{
    int i = blockIdx.x * blockDim.x + threadIdx.x;
    if (i < 2 * NNODE) ((int*)g_deg)[i] = 0;
}

__global__ void hist_kernel(const int* __restrict__ dst)
{
    const int et = blockIdx.y;
    int e = blockIdx.x * blockDim.x + threadIdx.x;
    if (e >= EE) return;
    atomicAdd(&g_deg[et][dst[(long)et * EE + e]], 1);
}

// phase A: per-block exclusive scan of 512 degs; local offsets + block totals
__global__ __launch_bounds__(SCB) void scanA_kernel()
{
    const int et = blockIdx.y;
    const int b = blockIdx.x;
    const int tid = threadIdx.x;
    const int idx = b * SCB + tid;
    const int lane = tid & 31, w = tid >> 5;

    int d = (idx < NNODE) ? g_deg[et][idx] : 0;
    int x = d;
    #pragma unroll
    for (int o = 1; o < 32; o <<= 1) {
        int n = __shfl_up_sync(0xffffffffu, x, o);
        if (lane >= o) x += n;
    }
    __shared__ int ws[SCB / 32];
    if (lane == 31) ws[w] = x;
    __syncthreads();
    if (w == 0) {
        int y = (lane < SCB / 32) ? ws[lane] : 0;
        #pragma unroll
        for (int o = 1; o < SCB / 32; o <<= 1) {
            int n = __shfl_up_sync(0xffffffffu, y, o);
            if (lane >= o) y += n;
        }
        if (lane < SCB / 32) ws[lane] = y;
    }
    __syncthreads();
    const int incl = x + (w > 0 ? ws[w - 1] : 0);
    if (idx < NNODE) g_rows[et][idx] = incl - d;
    if (tid == SCB - 1) g_bsum[et][b] = incl;
}

// phase B: scan the NSCB block totals (one block per etype)
__global__ __launch_bounds__(128) void scanB_kernel()
{
    const int et = blockIdx.x;
    const int t = threadIdx.x;
    const int lane = t & 31, w = t >> 5;
    int v = (t < NSCB) ? g_bsum[et][t] : 0;
    int x = v;
    #pragma unroll
    for (int o = 1; o < 32; o <<= 1) {
        int n = __shfl_up_sync(0xffffffffu, x, o);
        if (lane >= o) x += n;
    }
    __shared__ int ws[4];
    if (lane == 31) ws[w] = x;
    __syncthreads();
    int add = 0;
    #pragma unroll
    for (int i = 0; i < 4; ++i) if (i < w) add += ws[i];
    const int incl = x + add;
    if (t < NSCB) g_boff[et][t] = incl - v;
    if (t == NSCB - 1) g_rows[et][NNODE] = incl;
}

// phase C: add block offsets; emit rows + cursor
__global__ __launch_bounds__(SCB) void scanC_kernel()
{
    const int et = blockIdx.y;
    const int b = blockIdx.x;
    const int idx = b * SCB + threadIdx.x;
    if (idx >= NNODE) return;
    const int r = g_rows[et][idx] + g_boff[et][b];
    g_rows[et][idx] = r;
    g_cursor[et][idx] = r;
}

__global__ void scatter_kernel(const int* __restrict__ src, const int* __restrict__ dst)
{
    const int et = blockIdx.y;
    int e = blockIdx.x * blockDim.x + threadIdx.x;
    if (e >= EE) return;
    int s = src[(long)et * EE + e];
    int d = dst[(long)et * EE + e];
    int pos = atomicAdd(&g_cursor[et][d], 1);
    g_esrc[et][pos] = s;
}

// ======================= 3. warp-per-dst aggregation (2-edge unroll) ==============
__device__ __forceinline__ float dot8(const float4& qa, const float4& qb,
                                      const float4& ka, const float4& kb) {
    return qa.x * ka.x + qa.y * ka.y + qa.z * ka.z + qa.w * ka.w
         + qb.x * kb.x + qb.y * kb.y + qb.z * kb.z + qb.w * kb.w;
}

__global__ __launch_bounds__(256) void agg_kernel(const float* __restrict__ mu)
{
    const int et = blockIdx.y;
    const int dt = 1 - et;
    const int warp = threadIdx.x >> 5;
    const int lane = threadIdx.x & 31;
    const int node = blockIdx.x * 8 + warp;
    if (node >= NNODE) return;

    const int r0 = g_rows[et][node];
    const int r1 = g_rows[et][node + 1];

    const int h = lane >> 2;
    const int base = lane * 8;
    const float muh = mu[et * 8 + h] * ATT_SCALE;

    float acc[8];
    #pragma unroll
    for (int j = 0; j < 8; ++j) acc[j] = 0.f;
    float wsum = 0.f;

    if (r0 < r1) {
        const float* qrow = g_QKV[dt] + (size_t)node * QKVW + base;
        const float4 qa = *(const float4*)qrow;
        const float4 qb = *(const float4*)(qrow + 4);
        const int* __restrict__ ep = g_esrc[et];
        const float* __restrict__ kvbase = g_QKV[et];

        int j = r0;
        for (; j + 1 < r1; j += 2) {
            const int s0 = ep[j];
            const int s1 = ep[j + 1];
            const float* kr0 = kvbase + (size_t)s0 * QKVW + 256 + base;
            const float* kr1 = kvbase + (size_t)s1 * QKVW + 256 + base;
            float4 ka0 = *(const float4*)kr0;
            float4 kb0 = *(const float4*)(kr0 + 4);
            float4 va0 = *(const float4*)(kr0 + 256);
            float4 vb0 = *(const float4*)(kr0 + 260);
            float4 ka1 = *(const float4*)kr1;
            float4 kb1 = *(const float4*)(kr1 + 4);
            float4 va1 = *(const float4*)(kr1 + 256);
            float4 vb1 = *(const float4*)(kr1 + 260);

            float p0 = dot8(qa, qb, ka0, kb0);
            float p1 = dot8(qa, qb, ka1, kb1);
            p0 += __shfl_xor_sync(0xffffffffu, p0, 1);
            p1 += __shfl_xor_sync(0xffffffffu, p1, 1);
            p0 += __shfl_xor_sync(0xffffffffu, p0, 2);
            p1 += __shfl_xor_sync(0xffffffffu, p1, 2);

            float w0 = __expf(p0 * muh);
            float w1 = __expf(p1 * muh);
            wsum += w0 + w1;
            acc[0] += w0 * va0.x + w1 * va1.x;
            acc[1] += w0 * va0.y + w1 * va1.y;
            acc[2] += w0 * va0.z + w1 * va1.z;
            acc[3] += w0 * va0.w + w1 * va1.w;
            acc[4] += w0 * vb0.x + w1 * vb1.x;
            acc[5] += w0 * vb0.y + w1 * vb1.y;
            acc[6] += w0 * vb0.z + w1 * vb1.z;
            acc[7] += w0 * vb0.w + w1 * vb1.w;
        }
        if (j < r1) {
            const int s0 = ep[j];
            const float* kr0 = kvbase + (size_t)s0 * QKVW + 256 + base;
            float4 ka0 = *(const float4*)kr0;
            float4 kb0 = *(const float4*)(kr0 + 4);
            float4 va0 = *(const float4*)(kr0 + 256);
            float4 vb0 = *(const float4*)(kr0 + 260);
            float p0 = dot8(qa, qb, ka0, kb0);
            p0 += __shfl_xor_sync(0xffffffffu, p0, 1);
            p0 += __shfl_xor_sync(0xffffffffu, p0, 2);
            float w0 = __expf(p0 * muh);
            wsum += w0;
            acc[0] += w0 * va0.x;  acc[1] += w0 * va0.y;
            acc[2] += w0 * va0.z;  acc[3] += w0 * va0.w;
            acc[4] += w0 * vb0.x;  acc[5] += w0 * vb0.y;
            acc[6] += w0 * vb0.z;  acc[7] += w0 * vb0.w;
        }
    }

    const float inv = (wsum > 0.f) ? 1.f / wsum : 0.f;
    float* op = g_h[dt] + (size_t)node * DDIM + base;
    float4 o0 = make_float4(acc[0] * inv, acc[1] * inv, acc[2] * inv, acc[3] * inv);
    float4 o1 = make_float4(acc[4] * inv, acc[5] * inv, acc[6] * inv, acc[7] * inv);
    *(float4*)(op)     = o0;
    *(float4*)(op + 4) = o1;
}

// ======================= 4. split-bf16 HMMA GEMM (templated M-tile) ==============
// TM = 128: warp tile 64x32 (QKV, proven).  TM = 64: warp tile 32x32 (GEMM2,
// doubles CTA count to kill the 2.64-wave tail). Math identical.
#define BN 128
#define BK 64
#define LDS_STRIDE 72

template <int TM>
__global__ __launch_bounds__(256) void hmma_gemm_kernel(
    const float* __restrict__ A, long strideA,
    const __nv_bfloat16* __restrict__ Bhi, const __nv_bfloat16* __restrict__ Blo, long strideB,
    const float* __restrict__ bias, long strideBias,
    float* __restrict__ C, long strideC,
    int M, int Ntot)
{
    constexpr int MI = TM / 32;                       // m16 tiles per warp
    constexpr int AS_HI = 0;
    constexpr int AS_LO = TM * LDS_STRIDE * 2;
    constexpr int BS_HI = 2 * TM * LDS_STRIDE * 2;
    constexpr int BS_LO = BS_HI + BN * LDS_STRIDE * 2;

    extern __shared__ char smem[];
    const uint32_t sbase = smem_u32(smem);

    const int tid = threadIdx.x;
    const int wid = tid >> 5, lane = tid & 31;
    const int t = blockIdx.z;
    const int m0 = blockIdx.x * TM;
    const int n0 = blockIdx.y * BN;
    const int mw = (wid & 1) * (TM / 2);
    const int nw = (wid >> 1) * 32;

    A += (size_t)t * strideA;
    Bhi += (size_t)t * strideB;  Blo += (size_t)t * strideB;
    bias += (size_t)t * strideBias;
    C += (size_t)t * strideC;

    float acc[MI][4][4];
    #pragma unroll
    for (int i = 0; i < MI; ++i)
        #pragma unroll
        for (int j = 0; j < 4; ++j)
            #pragma unroll
            for (int r = 0; r < 4; ++r) acc[i][j][r] = 0.f;

    for (int kofs = 0; kofs < 256; kofs += BK) {
        __syncthreads();
        // ---- load A tile (TM x 64 fp32), split to hi/lo bf16 in registers ----
        #pragma unroll
        for (int i = 0; i < TM / 32; ++i) {
            int idx = tid + i * 256;
            int row = idx >> 3, c = (idx & 7) * 8;
            uint32_t soff = (uint32_t)(row * LDS_STRIDE + c) * 2;
            float4 v0 = make_float4(0.f, 0.f, 0.f, 0.f);
            float4 v1 = make_float4(0.f, 0.f, 0.f, 0.f);
            int gr = m0 + row;
            if (gr < M) {
                const float* ap = A + (size_t)gr * 256 + kofs + c;
                v0 = *(const float4*)ap;
                v1 = *(const float4*)(ap + 4);
            }
            uint4 hiq, loq;
            split8(v0, v1, hiq, loq);
            *(uint4*)(smem + AS_HI + soff) = hiq;
            *(uint4*)(smem + AS_LO + soff) = loq;
        }
        // ---- load B tile (128 x 64 hi & lo bf16) ----
        #pragma unroll
        for (int i = 0; i < 4; ++i) {
            int idx = tid + i * 256;
            int row = idx >> 3, c = (idx & 7) * 8;
            uint32_t soff = (uint32_t)(row * LDS_STRIDE + c) * 2;
            size_t s = (size_t)(n0 + row) * 256 + kofs + c;
            *(uint4*)(smem + BS_HI + soff) = *(const uint4*)(Bhi + s);
            *(uint4*)(smem + BS_LO + soff) = *(const uint4*)(Blo + s);
        }
        __syncthreads();

        #pragma unroll
        for (int kk = 0; kk < BK / 16; ++kk) {
            uint32_t a_hi[MI][4], a_lo[MI][4], b_hi[4][2], b_lo[4][2];
            #pragma unroll
            for (int i = 0; i < MI; ++i) {
                uint32_t off = (uint32_t)((mw + i * 16 + (lane & 15)) * LDS_STRIDE
                                          + kk * 16 + (lane >> 4) * 8) * 2;
                ldm_x4(a_hi[i], sbase + AS_HI + off);
                ldm_x4(a_lo[i], sbase + AS_LO + off);
            }
            #pragma unroll
            for (int j = 0; j < 4; ++j) {
                uint32_t off = (uint32_t)((nw + j * 8 + (lane & 7)) * LDS_STRIDE
                                          + kk * 16 + ((lane >> 3) & 1) * 8) * 2;
                ldm_x2(b_hi[j], sbase + BS_HI + off);
                ldm_x2(b_lo[j], sbase + BS_LO + off);
            }
            #pragma unroll
            for (int i = 0; i < MI; ++i)
                #pragma unroll
                for (int j = 0; j < 4; ++j) {
                    mma_bf16(acc[i][j], a_hi[i], b_hi[j]);
                    mma_bf16(acc[i][j], a_hi[i], b_lo[j]);
                    mma_bf16(acc[i][j], a_lo[i], b_hi[j]);
                }
        }
    }

    #pragma unroll
    for (int i = 0; i < MI; ++i) {
        int r0 = m0 + mw + i * 16 + (lane >> 2);
        int r1 = r0 + 8;
        #pragma unroll
        for (int j = 0; j < 4; ++j) {
            int col = n0 + nw + j * 8 + (lane & 3) * 2;
            float b0 = bias[col], b1 = bias[col + 1];
            if (r0 < M) {
                float2 o = make_float2(acc[i][j][0] + b0, acc[i][j][1] + b1);
                *(float2*)(C + (size_t)r0 * Ntot + col) = o;
            }
            if (r1 < M) {
                float2 o = make_float2(acc[i][j][2] + b0, acc[i][j][3] + b1);
                *(float2*)(C + (size_t)r1 * Ntot + col) = o;
            }
        }
    }
}

#define GEMM_SMEM_TM(TM) ((2 * (TM) + 2 * BN) * LDS_STRIDE * 2)

// ======================= 5. skip-mix + LayerNorm =================================
__global__ __launch_bounds__(256) void ln_kernel(
    const float* __restrict__ feats, const float* __restrict__ skip,
    const float* __restrict__ ln_w, const float* __restrict__ ln_b,
    float* __restrict__ out)
{
    long row = (long)blockIdx.x * 8 + (threadIdx.x >> 5);
    const int lane = threadIdx.x & 31;
    const int t = (int)(row / NNODE);
    const float alpha = 1.f / (1.f + expf(-skip[t]));
    const float beta = 1.f - alpha;

    const float* tr = (const float*)g_trans + row * DDIM + lane * 8;
    const float* ft = feats + row * DDIM + lane * 8;

    float v[8];
    float4 t0 = *(const float4*)(tr);
    float4 t1 = *(const float4*)(tr + 4);
    float4 f0 = *(const float4*)(ft);
    float4 f1 = *(const float4*)(ft + 4);
    v[0] = alpha * t0.x + beta * f0.x;  v[1] = alpha * t0.y + beta * f0.y;
    v[2] = alpha * t0.z + beta * f0.z;  v[3] = alpha * t0.w + beta * f0.w;
    v[4] = alpha * t1.x + beta * f1.x;  v[5] = alpha * t1.y + beta * f1.y;
    v[6] = alpha * t1.z + beta * f1.z;  v[7] = alpha * t1.w + beta * f1.w;

    float sum = 0.f, sq = 0.f;
    #pragma unroll
    for (int j = 0; j < 8; ++j) { sum += v[j]; sq += v[j] * v[j]; }
    #pragma unroll
    for (int o = 16; o > 0; o >>= 1) {
        sum += __shfl_xor_sync(0xffffffffu, sum, o);
        sq  += __shfl_xor_sync(0xffffffffu, sq, o);
    }
    const float mean = sum * (1.f / 256.f);
    const float var  = sq * (1.f / 256.f) - mean * mean;
    const float rstd = rsqrtf(var + 1e-5f);

    const int cbase = t * 256 + lane * 8;
    float* op = out + row * DDIM + lane * 8;
    float4 o0, o1;
    o0.x = (v[0] - mean) * rstd * ln_w[cbase + 0] + ln_b[cbase + 0];
    o0.y = (v[1] - mean) * rstd * ln_w[cbase + 1] + ln_b[cbase + 1];
    o0.z = (v[2] - mean) * rstd * ln_w[cbase + 2] + ln_b[cbase + 2];
    o0.w = (v[3] - mean) * rstd * ln_w[cbase + 3] + ln_b[cbase + 3];
    o1.x = (v[4] - mean) * rstd * ln_w[cbase + 4] + ln_b[cbase + 4];
    o1.y = (v[5] - mean) * rstd * ln_w[cbase + 5] + ln_b[cbase + 5];
    o1.z = (v[6] - mean) * rstd * ln_w[cbase + 6] + ln_b[cbase + 6];
    o1.w = (v[7] - mean) * rstd * ln_w[cbase + 7] + ln_b[cbase + 7];
    *(float4*)(op)     = o0;
    *(float4*)(op + 4) = o1;
}

// ======================= host launch =============================================
extern "C" void kernel_launch(void* const* d_in, const int* in_sizes, int n_in,
                              void* d_out, int out_size)
{
    const float* feats = (const float*)d_in[0];
    const float* Wk    = (const float*)d_in[1];
    const float* bk    = (const float*)d_in[2];
    const float* Wq    = (const float*)d_in[3];
    const float* bq    = (const float*)d_in[4];
    const float* Wv    = (const float*)d_in[5];
    const float* bv    = (const float*)d_in[6];
    const float* Wa    = (const float*)d_in[7];
    const float* ba    = (const float*)d_in[8];
    const float* ln_w  = (const float*)d_in[9];
    const float* ln_b  = (const float*)d_in[10];
    const float* skip  = (const float*)d_in[11];
    const float* mu    = (const float*)d_in[12];
    const float* w_att = (const float*)d_in[13];
    const float* w_msg = (const float*)d_in[14];
    const int*   src   = (const int*)d_in[15];
    const int*   dst   = (const int*)d_in[16];
    float* out = (float*)d_out;

    static bool attr_done = false;
    if (!attr_done) {
        cudaFuncSetAttribute(hmma_gemm_kernel<128>,
                             cudaFuncAttributeMaxDynamicSharedMemorySize, GEMM_SMEM_TM(128));
        cudaFuncSetAttribute(hmma_gemm_kernel<64>,
                             cudaFuncAttributeMaxDynamicSharedMemorySize, GEMM_SMEM_TM(64));
        attr_done = true;
    }

    float *pbcat, *pQKV, *ph, *ptrans;
    __nv_bfloat16 *pWcH, *pWcL, *pWaH, *pWaL;
    cudaGetSymbolAddress((void**)&pbcat, g_bcat);
    cudaGetSymbolAddress((void**)&pQKV, g_QKV);
    cudaGetSymbolAddress((void**)&ph, g_h);
    cudaGetSymbolAddress((void**)&ptrans, g_trans);
    cudaGetSymbolAddress((void**)&pWcH, g_WcatT_hi);
    cudaGetSymbolAddress((void**)&pWcL, g_WcatT_lo);
    cudaGetSymbolAddress((void**)&pWaH, g_WaT_hi);
    cudaGetSymbolAddress((void**)&pWaL, g_WaT_lo);

    // 1. weight prep
    {
        dim3 grid(1024, 2);
        prep_kernel<<<grid, 256>>>(Wk, bk, Wq, bq, Wv, bv, Wa, w_att, w_msg);
    }

    // 2. CSR build (multi-block scan)
    zerodeg_kernel<<<(2 * NNODE + 255) / 256, 256>>>();
    {
        dim3 grid((EE + 255) / 256, 2);
        hist_kernel<<<grid, 256>>>(dst);
    }
    {
        dim3 grid(NSCB, 2);
        scanA_kernel<<<grid, SCB>>>();
    }
    scanB_kernel<<<2, 128>>>();
    {
        dim3 grid(NSCB, 2);
        scanC_kernel<<<grid, SCB>>>();
    }
    {
        dim3 grid((EE + 255) / 256, 2);
        scatter_kernel<<<grid, 256>>>(src, dst);
    }

    // 3. QKV projection (TM=128, proven)
    {
        dim3 grid((NNODE + 127) / 128, QKVW / BN, 2);
        hmma_gemm_kernel<128><<<grid, 256, GEMM_SMEM_TM(128)>>>(
            feats, (long)NNODE * DDIM,
            pWcH, pWcL, (long)QKVW * DDIM,
            pbcat, (long)QKVW,
            pQKV, (long)NNODE * QKVW,
            NNODE, QKVW);
    }

    // 4. aggregation
    {
        dim3 grid((NNODE + 7) / 8, 2);
        agg_kernel<<<grid, 256>>>(mu);
    }

    // 5. output projection (TM=64: 3128 CTAs -> no tail wave)
    {
        dim3 grid((NNODE + 63) / 64, DDIM / BN, 2);
        hmma_gemm_kernel<64><<<grid, 256, GEMM_SMEM_TM(64)>>>(
            ph, (long)NNODE * DDIM,
            pWaH, pWaL, (long)DDIM * DDIM,
            ba, (long)DDIM,
            ptrans, (long)NNODE * DDIM,
            NNODE, DDIM);
    }

    // 6. skip-mix + LayerNorm -> d_out
    ln_kernel<<<(2 * NNODE) / 8, 256>>>(feats, skip, ln_w, ln_b, out);
}

// round 15
// speedup vs baseline: 1.0617x; 1.0117x over previous
#include <cuda_runtime.h>
#include <cuda_bf16.h>
#include <math.h>
#include <stdint.h>

#define NNODE 50000
#define DDIM  256
#define HH    8
#define EE    500000
#define QKVW  768
#define ATT_SCALE 0.17677669529663687f  // 1/sqrt(32)

#define SCB   512
#define NSCB  ((NNODE + SCB - 1) / SCB) // 98

// ======================= device scratch ==========================================
__device__ float g_bcat[2][QKVW];
__device__ __nv_bfloat16 g_WcatT_hi[2][(size_t)QKVW * DDIM];  // [n][k], n = Q|K'|V'
__device__ __nv_bfloat16 g_WcatT_lo[2][(size_t)QKVW * DDIM];
__device__ __nv_bfloat16 g_WaT_hi[2][(size_t)DDIM * DDIM];
__device__ __nv_bfloat16 g_WaT_lo[2][(size_t)DDIM * DDIM];
__device__ float g_QKV[2][(size_t)NNODE * QKVW];  // fp32: Q(256)|K'(256)|V'(256)
__device__ float g_h[2][(size_t)NNODE * DDIM];    // fp32 aggregated messages
// CSR-by-destination scratch
__device__ int g_deg[2][NNODE];
__device__ int g_rows[2][NNODE + 1];
__device__ int g_cursor[2][NNODE];
__device__ int g_esrc[2][EE];
__device__ int g_bsum[2][NSCB];
__device__ int g_boff[2][NSCB];

// ======================= PTX helpers (base-target safe) ==========================
__device__ __forceinline__ uint32_t smem_u32(const void* p) {
    uint32_t a;
    asm("{ .reg .u64 t; cvta.to.shared.u64 t, %1; cvt.u32.u64 %0, t; }" : "=r"(a) : "l"(p));
    return a;
}
__device__ __forceinline__ void ldm_x4(uint32_t* r, uint32_t addr) {
    asm volatile("ldmatrix.sync.aligned.m8n8.x4.shared.b16 {%0,%1,%2,%3}, [%4];"
                 : "=r"(r[0]), "=r"(r[1]), "=r"(r[2]), "=r"(r[3]) : "r"(addr));
}
__device__ __forceinline__ void ldm_x2(uint32_t* r, uint32_t addr) {
    asm volatile("ldmatrix.sync.aligned.m8n8.x2.shared.b16 {%0,%1}, [%2];"
                 : "=r"(r[0]), "=r"(r[1]) : "r"(addr));
}
__device__ __forceinline__ void mma_bf16(float* c, const uint32_t* a, const uint32_t* b) {
    asm volatile("mma.sync.aligned.m16n8k16.row.col.f32.bf16.bf16.f32 "
                 "{%0,%1,%2,%3}, {%4,%5,%6,%7}, {%8,%9}, {%0,%1,%2,%3};"
                 : "+f"(c[0]), "+f"(c[1]), "+f"(c[2]), "+f"(c[3])
                 : "r"(a[0]), "r"(a[1]), "r"(a[2]), "r"(a[3]), "r"(b[0]), "r"(b[1]));
}

// split 8 fp32 into bf16 hi/lo packed uint4s
__device__ __forceinline__ void split8(const float4& v0, const float4& v1,
                                       uint4& hiq, uint4& loq) {
    float f[8] = {v0.x, v0.y, v0.z, v0.w, v1.x, v1.y, v1.z, v1.w};
    __nv_bfloat162 hh[4], ll[4];
    #pragma unroll
    for (int j = 0; j < 4; ++j) {
        __nv_bfloat16 h0 = __float2bfloat16(f[2 * j]);
        __nv_bfloat16 h1 = __float2bfloat16(f[2 * j + 1]);
        __nv_bfloat16 l0 = __float2bfloat16(f[2 * j]     - __bfloat162float(h0));
        __nv_bfloat16 l1 = __float2bfloat16(f[2 * j + 1] - __bfloat162float(h1));
        hh[j] = __halves2bfloat162(h0, h1);
        ll[j] = __halves2bfloat162(l0, l1);
    }
    hiq = *(const uint4*)hh;
    loq = *(const uint4*)ll;
}

// ======================= 1. prep ==================================================
__global__ __launch_bounds__(256) void prep_kernel(
    const float* __restrict__ Wk, const float* __restrict__ bk,
    const float* __restrict__ Wq, const float* __restrict__ bq,
    const float* __restrict__ Wv, const float* __restrict__ bv,
    const float* __restrict__ Wa,
    const float* __restrict__ w_att, const float* __restrict__ w_msg)
{
    const int t = blockIdx.y;
    const int n = blockIdx.x;
    const int k = threadIdx.x;

    float val;
    if (n < 768) {
        if (n < 256) {
            val = Wq[((size_t)t * 256 + k) * 256 + n];
        } else {
            const int j = (n - 256) & 255;
            const int h = j >> 5, jj = j & 31;
            const float* W = (n < 512) ? Wk : Wv;
            const float* wm = ((n < 512) ? w_att : w_msg) + ((size_t)(t * 8 + h)) * 1024 + jj;
            const float* wrow = W + ((size_t)t * 256 + k) * 256 + h * 32;
            float a = 0.f;
            #pragma unroll 8
            for (int i = 0; i < 32; ++i) a += wrow[i] * wm[i * 32];
            val = a;
        }
        __nv_bfloat16 hi = __float2bfloat16(val);
        __nv_bfloat16 lo = __float2bfloat16(val - __bfloat162float(hi));
        g_WcatT_hi[t][(size_t)n * 256 + k] = hi;
        g_WcatT_lo[t][(size_t)n * 256 + k] = lo;
        if (k == 0) {
            float b;
            if (n < 256) b = bq[t * 256 + n];
            else {
                const int j = (n - 256) & 255;
                const int h = j >> 5, jj = j & 31;
                const float* bb = (n < 512) ? bk : bv;
                const float* wm = ((n < 512) ? w_att : w_msg) + ((size_t)(t * 8 + h)) * 1024 + jj;
                float a = 0.f;
                #pragma unroll 8
                for (int i = 0; i < 32; ++i) a += bb[t * 256 + h * 32 + i] * wm[i * 32];
                b = a;
            }
            g_bcat[t][n] = b;
        }
    } else {
        const int nn = n - 768;
        val = Wa[((size_t)t * 256 + k) * 256 + nn];
        __nv_bfloat16 hi = __float2bfloat16(val);
        __nv_bfloat16 lo = __float2bfloat16(val - __bfloat162float(hi));
        g_WaT_hi[t][(size_t)nn * 256 + k] = hi;
        g_WaT_lo[t][(size_t)nn * 256 + k] = lo;
    }
}

// ======================= 2. CSR build ============================================
__global__ void zerodeg_kernel()
{
    int i = blockIdx.x * blockDim.x + threadIdx.x;
    if (i < 2 * NNODE) ((int*)g_deg)[i] = 0;
}

__global__ void hist_kernel(const int* __restrict__ dst)
{
    const int et = blockIdx.y;
    int e = blockIdx.x * blockDim.x + threadIdx.x;
    if (e >= EE) return;
    atomicAdd(&g_deg[et][dst[(long)et * EE + e]], 1);
}

__global__ __launch_bounds__(SCB) void scanA_kernel()
{
    const int et = blockIdx.y;
    const int b = blockIdx.x;
    const int tid = threadIdx.x;
    const int idx = b * SCB + tid;
    const int lane = tid & 31, w = tid >> 5;

    int d = (idx < NNODE) ? g_deg[et][idx] : 0;
    int x = d;
    #pragma unroll
    for (int o = 1; o < 32; o <<= 1) {
        int n = __shfl_up_sync(0xffffffffu, x, o);
        if (lane >= o) x += n;
    }
    __shared__ int ws[SCB / 32];
    if (lane == 31) ws[w] = x;
    __syncthreads();
    if (w == 0) {
        int y = (lane < SCB / 32) ? ws[lane] : 0;
        #pragma unroll
        for (int o = 1; o < SCB / 32; o <<= 1) {
            int n = __shfl_up_sync(0xffffffffu, y, o);
            if (lane >= o) y += n;
        }
        if (lane < SCB / 32) ws[lane] = y;
    }
    __syncthreads();
    const int incl = x + (w > 0 ? ws[w - 1] : 0);
    if (idx < NNODE) g_rows[et][idx] = incl - d;
    if (tid == SCB - 1) g_bsum[et][b] = incl;
}

__global__ __launch_bounds__(128) void scanB_kernel()
{
    const int et = blockIdx.x;
    const int t = threadIdx.x;
    const int lane = t & 31, w = t >> 5;
    int v = (t < NSCB) ? g_bsum[et][t] : 0;
    int x = v;
    #pragma unroll
    for (int o = 1; o < 32; o <<= 1) {
        int n = __shfl_up_sync(0xffffffffu, x, o);
        if (lane >= o) x += n;
    }
    __shared__ int ws[4];
    if (lane == 31) ws[w] = x;
    __syncthreads();
    int add = 0;
    #pragma unroll
    for (int i = 0; i < 4; ++i) if (i < w) add += ws[i];
    const int incl = x + add;
    if (t < NSCB) g_boff[et][t] = incl - v;
    if (t == NSCB - 1) g_rows[et][NNODE] = incl;
}

__global__ __launch_bounds__(SCB) void scanC_kernel()
{
    const int et = blockIdx.y;
    const int b = blockIdx.x;
    const int idx = b * SCB + threadIdx.x;
    if (idx >= NNODE) return;
    const int r = g_rows[et][idx] + g_boff[et][b];
    g_rows[et][idx] = r;
    g_cursor[et][idx] = r;
}

__global__ void scatter_kernel(const int* __restrict__ src, const int* __restrict__ dst)
{
    const int et = blockIdx.y;
    int e = blockIdx.x * blockDim.x + threadIdx.x;
    if (e >= EE) return;
    int s = src[(long)et * EE + e];
    int d = dst[(long)et * EE + e];
    int pos = atomicAdd(&g_cursor[et][d], 1);
    g_esrc[et][pos] = s;
}

// ======================= 3. warp-per-dst aggregation ==============================
__device__ __forceinline__ float dot8(const float4& qa, const float4& qb,
                                      const float4& ka, const float4& kb) {
    return qa.x * ka.x + qa.y * ka.y + qa.z * ka.z + qa.w * ka.w
         + qb.x * kb.x + qb.y * kb.y + qb.z * kb.z + qb.w * kb.w;
}

__global__ __launch_bounds__(256) void agg_kernel(const float* __restrict__ mu)
{
    const int et = blockIdx.y;
    const int dt = 1 - et;
    const int warp = threadIdx.x >> 5;
    const int lane = threadIdx.x & 31;
    const int node = blockIdx.x * 8 + warp;
    if (node >= NNODE) return;

    const int r0 = g_rows[et][node];
    const int r1 = g_rows[et][node + 1];

    const int h = lane >> 2;
    const int base = lane * 8;
    const float muh = mu[et * 8 + h] * ATT_SCALE;

    float acc[8];
    #pragma unroll
    for (int j = 0; j < 8; ++j) acc[j] = 0.f;
    float wsum = 0.f;

    if (r0 < r1) {
        const float* qrow = g_QKV[dt] + (size_t)node * QKVW + base;
        const float4 qa = *(const float4*)qrow;
        const float4 qb = *(const float4*)(qrow + 4);
        const int* __restrict__ ep = g_esrc[et];
        const float* __restrict__ kvbase = g_QKV[et];

        int j = r0;
        for (; j + 1 < r1; j += 2) {
            const int s0 = ep[j];
            const int s1 = ep[j + 1];
            const float* kr0 = kvbase + (size_t)s0 * QKVW + 256 + base;
            const float* kr1 = kvbase + (size_t)s1 * QKVW + 256 + base;
            float4 ka0 = *(const float4*)kr0;
            float4 kb0 = *(const float4*)(kr0 + 4);
            float4 va0 = *(const float4*)(kr0 + 256);
            float4 vb0 = *(const float4*)(kr0 + 260);
            float4 ka1 = *(const float4*)kr1;
            float4 kb1 = *(const float4*)(kr1 + 4);
            float4 va1 = *(const float4*)(kr1 + 256);
            float4 vb1 = *(const float4*)(kr1 + 260);

            float p0 = dot8(qa, qb, ka0, kb0);
            float p1 = dot8(qa, qb, ka1, kb1);
            p0 += __shfl_xor_sync(0xffffffffu, p0, 1);
            p1 += __shfl_xor_sync(0xffffffffu, p1, 1);
            p0 += __shfl_xor_sync(0xffffffffu, p0, 2);
            p1 += __shfl_xor_sync(0xffffffffu, p1, 2);

            float w0 = __expf(p0 * muh);
            float w1 = __expf(p1 * muh);
            wsum += w0 + w1;
            acc[0] += w0 * va0.x + w1 * va1.x;
            acc[1] += w0 * va0.y + w1 * va1.y;
            acc[2] += w0 * va0.z + w1 * va1.z;
            acc[3] += w0 * va0.w + w1 * va1.w;
            acc[4] += w0 * vb0.x + w1 * vb1.x;
            acc[5] += w0 * vb0.y + w1 * vb1.y;
            acc[6] += w0 * vb0.z + w1 * vb1.z;
            acc[7] += w0 * vb0.w + w1 * vb1.w;
        }
        if (j < r1) {
            const int s0 = ep[j];
            const float* kr0 = kvbase + (size_t)s0 * QKVW + 256 + base;
            float4 ka0 = *(const float4*)kr0;
            float4 kb0 = *(const float4*)(kr0 + 4);
            float4 va0 = *(const float4*)(kr0 + 256);
            float4 vb0 = *(const float4*)(kr0 + 260);
            float p0 = dot8(qa, qb, ka0, kb0);
            p0 += __shfl_xor_sync(0xffffffffu, p0, 1);
            p0 += __shfl_xor_sync(0xffffffffu, p0, 2);
            float w0 = __expf(p0 * muh);
            wsum += w0;
            acc[0] += w0 * va0.x;  acc[1] += w0 * va0.y;
            acc[2] += w0 * va0.z;  acc[3] += w0 * va0.w;
            acc[4] += w0 * vb0.x;  acc[5] += w0 * vb0.y;
            acc[6] += w0 * vb0.z;  acc[7] += w0 * vb0.w;
        }
    }

    const float inv = (wsum > 0.f) ? 1.f / wsum : 0.f;
    float* op = g_h[dt] + (size_t)node * DDIM + base;
    float4 o0 = make_float4(acc[0] * inv, acc[1] * inv, acc[2] * inv, acc[3] * inv);
    float4 o1 = make_float4(acc[4] * inv, acc[5] * inv, acc[6] * inv, acc[7] * inv);
    *(float4*)(op)     = o0;
    *(float4*)(op + 4) = o1;
}

// ======================= 4. QKV split-bf16 HMMA GEMM (TM=128, proven) ============
#define BN 128
#define BK 64
#define LDS_STRIDE 72
#define Q_AS_HI 0
#define Q_AS_LO (128 * LDS_STRIDE * 2)
#define Q_BS_HI (2 * 128 * LDS_STRIDE * 2)
#define Q_BS_LO (Q_BS_HI + BN * LDS_STRIDE * 2)
#define QKV_SMEM ((2 * 128 + 2 * BN) * LDS_STRIDE * 2)

__global__ __launch_bounds__(256) void hmma_gemm_kernel(
    const float* __restrict__ A, long strideA,
    const __nv_bfloat16* __restrict__ Bhi, const __nv_bfloat16* __restrict__ Blo, long strideB,
    const float* __restrict__ bias, long strideBias,
    float* __restrict__ C, long strideC,
    int M, int Ntot)
{
    extern __shared__ char smem[];
    const uint32_t sbase = smem_u32(smem);

    const int tid = threadIdx.x;
    const int wid = tid >> 5, lane = tid & 31;
    const int t = blockIdx.z;
    const int m0 = blockIdx.x * 128;
    const int n0 = blockIdx.y * BN;
    const int mw = (wid & 1) * 64;
    const int nw = (wid >> 1) * 32;

    A += (size_t)t * strideA;
    Bhi += (size_t)t * strideB;  Blo += (size_t)t * strideB;
    bias += (size_t)t * strideBias;
    C += (size_t)t * strideC;

    float acc[4][4][4];
    #pragma unroll
    for (int i = 0; i < 4; ++i)
        #pragma unroll
        for (int j = 0; j < 4; ++j)
            #pragma unroll
            for (int r = 0; r < 4; ++r) acc[i][j][r] = 0.f;

    for (int kofs = 0; kofs < 256; kofs += BK) {
        __syncthreads();
        #pragma unroll
        for (int i = 0; i < 4; ++i) {
            int idx = tid + i * 256;
            int row = idx >> 3, c = (idx & 7) * 8;
            uint32_t soff = (uint32_t)(row * LDS_STRIDE + c) * 2;
            float4 v0 = make_float4(0.f, 0.f, 0.f, 0.f);
            float4 v1 = make_float4(0.f, 0.f, 0.f, 0.f);
            int gr = m0 + row;
            if (gr < M) {
                const float* ap = A + (size_t)gr * 256 + kofs + c;
                v0 = *(const float4*)ap;
                v1 = *(const float4*)(ap + 4);
            }
            uint4 hiq, loq;
            split8(v0, v1, hiq, loq);
            *(uint4*)(smem + Q_AS_HI + soff) = hiq;
            *(uint4*)(smem + Q_AS_LO + soff) = loq;
        }
        #pragma unroll
        for (int i = 0; i < 4; ++i) {
            int idx = tid + i * 256;
            int row = idx >> 3, c = (idx & 7) * 8;
            uint32_t soff = (uint32_t)(row * LDS_STRIDE + c) * 2;
            size_t s = (size_t)(n0 + row) * 256 + kofs + c;
            *(uint4*)(smem + Q_BS_HI + soff) = *(const uint4*)(Bhi + s);
            *(uint4*)(smem + Q_BS_LO + soff) = *(const uint4*)(Blo + s);
        }
        __syncthreads();

        #pragma unroll
        for (int kk = 0; kk < BK / 16; ++kk) {
            uint32_t a_hi[4][4], a_lo[4][4], b_hi[4][2], b_lo[4][2];
            #pragma unroll
            for (int i = 0; i < 4; ++i) {
                uint32_t off = (uint32_t)((mw + i * 16 + (lane & 15)) * LDS_STRIDE
                                          + kk * 16 + (lane >> 4) * 8) * 2;
                ldm_x4(a_hi[i], sbase + Q_AS_HI + off);
                ldm_x4(a_lo[i], sbase + Q_AS_LO + off);
            }
            #pragma unroll
            for (int j = 0; j < 4; ++j) {
                uint32_t off = (uint32_t)((nw + j * 8 + (lane & 7)) * LDS_STRIDE
                                          + kk * 16 + ((lane >> 3) & 1) * 8) * 2;
                ldm_x2(b_hi[j], sbase + Q_BS_HI + off);
                ldm_x2(b_lo[j], sbase + Q_BS_LO + off);
            }
            #pragma unroll
            for (int i = 0; i < 4; ++i)
                #pragma unroll
                for (int j = 0; j < 4; ++j) {
                    mma_bf16(acc[i][j], a_hi[i], b_hi[j]);
                    mma_bf16(acc[i][j], a_hi[i], b_lo[j]);
                    mma_bf16(acc[i][j], a_lo[i], b_hi[j]);
                }
        }
    }

    #pragma unroll
    for (int i = 0; i < 4; ++i) {
        int r0 = m0 + mw + i * 16 + (lane >> 2);
        int r1 = r0 + 8;
        #pragma unroll
        for (int j = 0; j < 4; ++j) {
            int col = n0 + nw + j * 8 + (lane & 3) * 2;
            float b0 = bias[col], b1 = bias[col + 1];
            if (r0 < M) {
                float2 o = make_float2(acc[i][j][0] + b0, acc[i][j][1] + b1);
                *(float2*)(C + (size_t)r0 * Ntot + col) = o;
            }
            if (r1 < M) {
                float2 o = make_float2(acc[i][j][2] + b0, acc[i][j][3] + b1);
                *(float2*)(C + (size_t)r1 * Ntot + col) = o;
            }
        }
    }
}

// ======================= 5. GEMM2 + skip-mix + LayerNorm (fused) =================
// Tile 64 x 256 (full row per CTA). 8 warps = 2m x 4n, warp tile 32x64.
// out[r] = LN(alpha*(h@Wa + ba) + (1-alpha)*feats[r]) * ln_w + ln_b
#define G2_AS_HI 0
#define G2_AS_LO (64 * LDS_STRIDE * 2)                 // 9216
#define G2_BS_HI (2 * 64 * LDS_STRIDE * 2)             // 18432
#define G2_BS_LO (G2_BS_HI + 256 * LDS_STRIDE * 2)     // 55296
#define G2_SMEM  (G2_BS_LO + 256 * LDS_STRIDE * 2)     // 92160

__global__ __launch_bounds__(256, 2) void gemm2_ln_kernel(
    const float* __restrict__ ba,
    const float* __restrict__ feats, const float* __restrict__ skip,
    const float* __restrict__ ln_w, const float* __restrict__ ln_b,
    float* __restrict__ out)
{
    extern __shared__ char smem[];
    const uint32_t sbase = smem_u32(smem);

    const int tid = threadIdx.x;
    const int wid = tid >> 5, lane = tid & 31;
    const int t = blockIdx.y;
    const int m0 = blockIdx.x * 64;
    const int mw = (wid & 1) * 32;            // warp m offset (0/32)
    const int nw = (wid >> 1) * 64;           // warp n offset (0/64/128/192)

    const float* A = g_h[t];
    const __nv_bfloat16* Bhi = g_WaT_hi[t];
    const __nv_bfloat16* Blo = g_WaT_lo[t];
    const float* fbase = feats + (size_t)t * NNODE * DDIM;
    float* obase = out + (size_t)t * NNODE * DDIM;

    float acc[2][8][4];
    #pragma unroll
    for (int i = 0; i < 2; ++i)
        #pragma unroll
        for (int j = 0; j < 8; ++j)
            #pragma unroll
            for (int r = 0; r < 4; ++r) acc[i][j][r] = 0.f;

    for (int kofs = 0; kofs < 256; kofs += BK) {
        __syncthreads();
        // A tile: 64 x 64 fp32 -> hi/lo (512 chunks of 8 elems; 2 iters)
        #pragma unroll
        for (int i = 0; i < 2; ++i) {
            int idx = tid + i * 256;
            int row = idx >> 3, c = (idx & 7) * 8;
            uint32_t soff = (uint32_t)(row * LDS_STRIDE + c) * 2;
            float4 v0 = make_float4(0.f, 0.f, 0.f, 0.f);
            float4 v1 = make_float4(0.f, 0.f, 0.f, 0.f);
            int gr = m0 + row;
            if (gr < NNODE) {
                const float* ap = A + (size_t)gr * 256 + kofs + c;
                v0 = *(const float4*)ap;
                v1 = *(const float4*)(ap + 4);
            }
            uint4 hiq, loq;
            split8(v0, v1, hiq, loq);
            *(uint4*)(smem + G2_AS_HI + soff) = hiq;
            *(uint4*)(smem + G2_AS_LO + soff) = loq;
        }
        // B tile: 256 rows x 64 bf16, hi & lo (2048 chunks each; 8 iters each)
        #pragma unroll
        for (int i = 0; i < 8; ++i) {
            int idx = tid + i * 256;
            int row = idx >> 3, c = (idx & 7) * 8;
            uint32_t soff = (uint32_t)(row * LDS_STRIDE + c) * 2;
            size_t s = (size_t)row * 256 + kofs + c;
            *(uint4*)(smem + G2_BS_HI + soff) = *(const uint4*)(Bhi + s);
            *(uint4*)(smem + G2_BS_LO + soff) = *(const uint4*)(Blo + s);
        }
        __syncthreads();

        #pragma unroll
        for (int kk = 0; kk < BK / 16; ++kk) {
            uint32_t a_hi[2][4], a_lo[2][4];
            #pragma unroll
            for (int i = 0; i < 2; ++i) {
                uint32_t off = (uint32_t)((mw + i * 16 + (lane & 15)) * LDS_STRIDE
                                          + kk * 16 + (lane >> 4) * 8) * 2;
                ldm_x4(a_hi[i], sbase + G2_AS_HI + off);
                ldm_x4(a_lo[i], sbase + G2_AS_LO + off);
            }
            // process B in two j-halves to limit register liveness
            #pragma unroll
            for (int jh = 0; jh < 2; ++jh) {
                uint32_t b_hi[4][2], b_lo[4][2];
                #pragma unroll
                for (int jj = 0; jj < 4; ++jj) {
                    int j = jh * 4 + jj;
                    uint32_t off = (uint32_t)((nw + j * 8 + (lane & 7)) * LDS_STRIDE
                                              + kk * 16 + ((lane >> 3) & 1) * 8) * 2;
                    ldm_x2(b_hi[jj], sbase + G2_BS_HI + off);
                    ldm_x2(b_lo[jj], sbase + G2_BS_LO + off);
                }
                #pragma unroll
                for (int i = 0; i < 2; ++i)
                    #pragma unroll
                    for (int jj = 0; jj < 4; ++jj) {
                        mma_bf16(acc[i][jh * 4 + jj], a_hi[i], b_hi[jj]);
                        mma_bf16(acc[i][jh * 4 + jj], a_hi[i], b_lo[jj]);
                        mma_bf16(acc[i][jh * 4 + jj], a_lo[i], b_hi[jj]);
                    }
            }
        }
    }

    // ================= fused epilogue: bias + skip-mix + LayerNorm ================
    __syncthreads();                          // smem reuse safe after this
    const float alpha = 1.f / (1.f + expf(-skip[t]));
    const float beta = 1.f - alpha;

    // 1. mix into acc, accumulate per-row partial sums over this thread's 16 cols
    float rsum[2][2] = {{0.f, 0.f}, {0.f, 0.f}};
    float rsq[2][2]  = {{0.f, 0.f}, {0.f, 0.f}};
    #pragma unroll
    for (int i = 0; i < 2; ++i) {
        const int rr0 = m0 + mw + i * 16 + (lane >> 2);
        const int rr1 = rr0 + 8;
        #pragma unroll
        for (int j = 0; j < 8; ++j) {
            const int col = nw + j * 8 + (lane & 3) * 2;
            const float b0 = ba[t * 256 + col], b1 = ba[t * 256 + col + 1];
            float v0 = 0.f, v1 = 0.f, v2 = 0.f, v3 = 0.f;
            if (rr0 < NNODE) {
                const float2 f = *(const float2*)(fbase + (size_t)rr0 * 256 + col);
                v0 = alpha * (acc[i][j][0] + b0) + beta * f.x;
                v1 = alpha * (acc[i][j][1] + b1) + beta * f.y;
            }
            if (rr1 < NNODE) {
                const float2 f = *(const float2*)(fbase + (size_t)rr1 * 256 + col);
                v2 = alpha * (acc[i][j][2] + b0) + beta * f.x;
                v3 = alpha * (acc[i][j][3] + b1) + beta * f.y;
            }
            acc[i][j][0] = v0; acc[i][j][1] = v1;
            acc[i][j][2] = v2; acc[i][j][3] = v3;
            rsum[i][0] += v0 + v1;  rsq[i][0] += v0 * v0 + v1 * v1;
            rsum[i][1] += v2 + v3;  rsq[i][1] += v2 * v2 + v3 * v3;
        }
    }
    // 2. reduce within the 4-lane row group
    #pragma unroll
    for (int o = 1; o <= 2; o <<= 1) {
        #pragma unroll
        for (int i = 0; i < 2; ++i)
            #pragma unroll
            for (int r = 0; r < 2; ++r) {
                rsum[i][r] += __shfl_xor_sync(0xffffffffu, rsum[i][r], o);
                rsq[i][r]  += __shfl_xor_sync(0xffffffffu, rsq[i][r], o);
            }
    }
    // 3. exchange across the 4 n-warps via smem: part[row64][nwarp]
    float2* part = (float2*)smem;
    if ((lane & 3) == 0) {
        #pragma unroll
        for (int i = 0; i < 2; ++i) {
            const int row = mw + i * 16 + (lane >> 2);
            part[(row) * 4 + (wid >> 1)]     = make_float2(rsum[i][0], rsq[i][0]);
            part[(row + 8) * 4 + (wid >> 1)] = make_float2(rsum[i][1], rsq[i][1]);
        }
    }
    __syncthreads();
    // 4. final stats + normalize + write
    #pragma unroll
    for (int i = 0; i < 2; ++i) {
        #pragma unroll
        for (int r = 0; r < 2; ++r) {
            const int row = mw + i * 16 + (lane >> 2) + r * 8;
            const int gr = m0 + row;
            if (gr >= NNODE) continue;
            float s = 0.f, q = 0.f;
            #pragma unroll
            for (int w = 0; w < 4; ++w) {
                const float2 p = part[row * 4 + w];
                s += p.x;  q += p.y;
            }
            const float mean = s * (1.f / 256.f);
            const float var = q * (1.f / 256.f) - mean * mean;
            const float rstd = rsqrtf(var + 1e-5f);
            #pragma unroll
            for (int j = 0; j < 8; ++j) {
                const int col = nw + j * 8 + (lane & 3) * 2;
                const float lw0 = ln_w[t * 256 + col], lw1 = ln_w[t * 256 + col + 1];
                const float lb0 = ln_b[t * 256 + col], lb1 = ln_b[t * 256 + col + 1];
                const float v0 = acc[i][j][r * 2], v1 = acc[i][j][r * 2 + 1];
                float2 o;
                o.x = (v0 - mean) * rstd * lw0 + lb0;
                o.y = (v1 - mean) * rstd * lw1 + lb1;
                *(float2*)(obase + (size_t)gr * 256 + col) = o;
            }
        }
    }
}

// ======================= host launch =============================================
extern "C" void kernel_launch(void* const* d_in, const int* in_sizes, int n_in,
                              void* d_out, int out_size)
{
    const float* feats = (const float*)d_in[0];
    const float* Wk    = (const float*)d_in[1];
    const float* bk    = (const float*)d_in[2];
    const float* Wq    = (const float*)d_in[3];
    const float* bq    = (const float*)d_in[4];
    const float* Wv    = (const float*)d_in[5];
    const float* bv    = (const float*)d_in[6];
    const float* Wa    = (const float*)d_in[7];
    const float* ba    = (const float*)d_in[8];
    const float* ln_w  = (const float*)d_in[9];
    const float* ln_b  = (const float*)d_in[10];
    const float* skip  = (const float*)d_in[11];
    const float* mu    = (const float*)d_in[12];
    const float* w_att = (const float*)d_in[13];
    const float* w_msg = (const float*)d_in[14];
    const int*   src   = (const int*)d_in[15];
    const int*   dst   = (const int*)d_in[16];
    float* out = (float*)d_out;

    static bool attr_done = false;
    if (!attr_done) {
        cudaFuncSetAttribute(hmma_gemm_kernel,
                             cudaFuncAttributeMaxDynamicSharedMemorySize, QKV_SMEM);
        cudaFuncSetAttribute(gemm2_ln_kernel,
                             cudaFuncAttributeMaxDynamicSharedMemorySize, G2_SMEM);
        attr_done = true;
    }

    float *pbcat, *pQKV;
    __nv_bfloat16 *pWcH, *pWcL;
    cudaGetSymbolAddress((void**)&pbcat, g_bcat);
    cudaGetSymbolAddress((void**)&pQKV, g_QKV);
    cudaGetSymbolAddress((void**)&pWcH, g_WcatT_hi);
    cudaGetSymbolAddress((void**)&pWcL, g_WcatT_lo);

    // 1. weight prep
    {
        dim3 grid(1024, 2);
        prep_kernel<<<grid, 256>>>(Wk, bk, Wq, bq, Wv, bv, Wa, w_att, w_msg);
    }

    // 2. CSR build
    zerodeg_kernel<<<(2 * NNODE + 255) / 256, 256>>>();
    {
        dim3 grid((EE + 255) / 256, 2);
        hist_kernel<<<grid, 256>>>(dst);
    }
    {
        dim3 grid(NSCB, 2);
        scanA_kernel<<<grid, SCB>>>();
    }
    scanB_kernel<<<2, 128>>>();
    {
        dim3 grid(NSCB, 2);
        scanC_kernel<<<grid, SCB>>>();
    }
    {
        dim3 grid((EE + 255) / 256, 2);
        scatter_kernel<<<grid, 256>>>(src, dst);
    }

    // 3. QKV projection (TM=128, proven)
    {
        dim3 grid((NNODE + 127) / 128, QKVW / BN, 2);
        hmma_gemm_kernel<<<grid, 256, QKV_SMEM>>>(
            feats, (long)NNODE * DDIM,
            pWcH, pWcL, (long)QKVW * DDIM,
            pbcat, (long)QKVW,
            pQKV, (long)NNODE * QKVW,
            NNODE, QKVW);
    }

    // 4. aggregation
    {
        dim3 grid((NNODE + 7) / 8, 2);
        agg_kernel<<<grid, 256>>>(mu);
    }

    // 5. output projection + skip-mix + LayerNorm (fully fused) -> d_out
    {
        dim3 grid((NNODE + 63) / 64, 2);
        gemm2_ln_kernel<<<grid, 256, G2_SMEM>>>(ba, feats, skip, ln_w, ln_b, out);
    }
}